// round 6
// baseline (speedup 1.0000x reference)
#include <cuda_runtime.h>
#include <cuda_bf16.h>

// TGSM v6: kernel1 = 3-warp pipelined scan (W0 recurrence, W1 GCN+LN-stats,
// W2 apply+ELU+store ge); kernel2 = exact softmax pool + Jacobi + classifier.
// B=1024, T=256, N=14, Fd=4, H=32, K=5, C=2

#define Bn 1024
#define Tn 256
#define Nn 14
#define Hn 32

__device__ float g_ge[Bn * Tn * Hn];     // per-step channel means
__device__ float g_esm[Bn * Nn * Nn];    // final edge-state matrices

__device__ __forceinline__ float warp_sum(float v) {
    v += __shfl_xor_sync(0xffffffffu, v, 16);
    v += __shfl_xor_sync(0xffffffffu, v, 8);
    v += __shfl_xor_sync(0xffffffffu, v, 4);
    v += __shfl_xor_sync(0xffffffffu, v, 2);
    v += __shfl_xor_sync(0xffffffffu, v, 1);
    return v;
}
__device__ __forceinline__ float warp_max(float v) {
    v = fmaxf(v, __shfl_xor_sync(0xffffffffu, v, 16));
    v = fmaxf(v, __shfl_xor_sync(0xffffffffu, v, 8));
    v = fmaxf(v, __shfl_xor_sync(0xffffffffu, v, 4));
    v = fmaxf(v, __shfl_xor_sync(0xffffffffu, v, 2));
    v = fmaxf(v, __shfl_xor_sync(0xffffffffu, v, 1));
    return v;
}
__device__ __forceinline__ float elu(float y) {
    return (y > 0.0f) ? y : (__expf(y) - 1.0f);
}
// sigmoid(x) = 0.5 + 0.5 * tanh(x/2), single MUFU op
__device__ __forceinline__ float sigmoid_fast(float x) {
    float th;
    asm("tanh.approx.f32 %0, %1;" : "=f"(th) : "f"(0.5f * x));
    return fmaf(0.5f, th, 0.5f);
}

// ===================== Kernel 1: pipelined temporal scan =====================
__global__ __launch_bounds__(96, 7)
void tgsm_scan(const float* __restrict__ ws,
               const float* __restrict__ gate_w, const float* __restrict__ gate_b,
               const float* __restrict__ gcn_w,  const float* __restrict__ gcn_b,
               const float* __restrict__ ln_g,   const float* __restrict__ ln_b)
{
    const int b    = blockIdx.x;
    const int tid  = threadIdx.x;
    const int lane = tid & 31;
    const int warp = tid >> 5;     // 0: recurrence, 1: matvec+stats, 2: apply
    const int idx  = lane & 15;

    __shared__ float4 s_nrm[16];            // W0-internal
    __shared__ float4 s_q[2][16];           // W0 -> W1
    __shared__ float  s_dis[2][16];         // W0 -> W1
    __shared__ float  s_e[2][Nn][16];       // W0 -> W1 (s_e[buf][m][r] = esm[r][m])
    __shared__ float4 s_xp[2][16];          // W1 -> W2
    __shared__ float2 s_mr[2][16];          // W1 -> W2
    __shared__ float  s_G[25];              // Gram of [W;b] rows (W1)
    __shared__ float  s_SWb[5];             // row sums of [W;b] (W1)

    // ---- per-warp constants ----
    float gw0 = 0.f, gw1 = 0.f, gbv = 0.f;
    float Wc0 = 0.f, Wc1 = 0.f, Wc2 = 0.f, Wc3 = 0.f, gcnb = 0.f;
    float lng = 0.f, lnb = 0.f;

    if (warp == 0) {
        gw0 = gate_w[0]; gw1 = gate_w[1]; gbv = gate_b[0];
    } else {
        Wc0 = gcn_w[0 * Hn + lane];
        Wc1 = gcn_w[1 * Hn + lane];
        Wc2 = gcn_w[2 * Hn + lane];
        Wc3 = gcn_w[3 * Hn + lane];
        gcnb = gcn_b[lane];
        if (warp == 1) {
            float vW[5] = {Wc0, Wc1, Wc2, Wc3, gcnb};
            #pragma unroll
            for (int i2 = 0; i2 < 5; i2++) {
                #pragma unroll
                for (int j2 = i2; j2 < 5; j2++) {
                    float g = warp_sum(vW[i2] * vW[j2]);
                    if (lane == 0) { s_G[i2*5+j2] = g; s_G[j2*5+i2] = g; }
                }
                float sw = warp_sum(vW[i2]);
                if (lane == 0) s_SWb[i2] = sw;
            }
        } else {
            lng = ln_g[lane]; lnb = ln_b[lane];
        }
    }

    // W0 state: esm column `lane` (symmetric)
    float e[Nn];
    #pragma unroll
    for (int i2 = 0; i2 < Nn; i2++) e[i2] = 0.0f;

    const float4* src = reinterpret_cast<const float4*>(ws) + (size_t)b * Tn * Nn;
    float4 dcur = make_float4(0.f,0.f,0.f,0.f);
    float4 dnxt = make_float4(0.f,0.f,0.f,0.f);
    if (warp == 0 && lane < Nn) dcur = src[lane];

    __syncthreads();   // s_G / s_SWb visible

    for (int i = 0; i < Tn + 2; i++) {
        if (warp == 0) {
            if (i < Tn) {
                // phase 1: normalize de; prefetch next
                float4 de = dcur;
                if (lane < Nn && i + 1 < Tn) dnxt = src[(i + 1) * Nn + lane];
                float d2  = de.x*de.x + de.y*de.y + de.z*de.z + de.w*de.w;
                float inv = rsqrtf(fmaxf(d2, 1e-24f));
                float4 nrm = make_float4(de.x*inv, de.y*inv, de.z*inv, de.w*inv);
                if (lane < Nn) s_nrm[lane] = nrm;
                __syncwarp();

                // phase 2: adjacency + gate + esm update + rowsum; publish e
                const int buf = i & 1;
                float rowsum = 1.0f;
                #pragma unroll
                for (int n = 0; n < Nn; n++) {
                    float4 nn4 = s_nrm[n];
                    float dot = nrm.x*nn4.x;
                    dot = fmaf(nrm.y, nn4.y, dot);
                    dot = fmaf(nrm.z, nn4.z, dot);
                    dot = fmaf(nrm.w, nn4.w, dot);
                    float adj = fmaf(dot, 0.5f, 0.5f);
                    adj = (n == lane) ? 0.0f : adj;
                    float ee = e[n];
                    float xg = fmaf(gw0, ee, fmaf(gw1, adj, gbv));
                    float z  = sigmoid_fast(xg);
                    ee = fmaf(z, adj - ee, ee);
                    e[n] = ee;
                    rowsum += ee;
                    if (lane < Nn) s_e[buf][n][lane] = ee;
                }
                float dis = rsqrtf(fmaxf(rowsum, 1e-6f));
                if (lane < Nn) {
                    s_q[buf][lane]   = make_float4(de.x*dis, de.y*dis, de.z*dis, de.w*dis);
                    s_dis[buf][lane] = dis;
                }
                dcur = dnxt;
            }
        } else if (warp == 1) {
            if (i >= 1 && i <= Tn) {
                const int buf = (i - 1) & 1;
                // p = esm @ q (row = idx), racc = rowsum(esm.dis)
                float4 p = make_float4(0.f,0.f,0.f,0.f);
                float racc = 0.0f;
                #pragma unroll
                for (int m = 0; m < Nn; m++) {
                    float em  = s_e[buf][m][idx];
                    float4 qm = s_q[buf][m];
                    float dm  = s_dis[buf][m];
                    p.x = fmaf(em, qm.x, p.x);
                    p.y = fmaf(em, qm.y, p.y);
                    p.z = fmaf(em, qm.z, p.z);
                    p.w = fmaf(em, qm.w, p.w);
                    racc = fmaf(em, dm, racc);
                }
                if (lane < Nn) {
                    float dis = s_dis[buf][lane];
                    float4 q  = s_q[buf][lane];
                    float rr = dis * (racc + dis);
                    float x0 = (p.x + q.x) * dis;
                    float x1 = (p.y + q.y) * dis;
                    float x2 = (p.z + q.z) * dis;
                    float x3 = (p.w + q.w) * dis;
                    float mu = (x0*s_SWb[0] + x1*s_SWb[1] + x2*s_SWb[2]
                              + x3*s_SWb[3] + rr*s_SWb[4]) * (1.0f/32.0f);
                    float xt[5] = {x0, x1, x2, x3, rr};
                    float s2 = 0.0f;
                    #pragma unroll
                    for (int ii = 0; ii < 5; ii++) {
                        float rowd = 0.0f;
                        #pragma unroll
                        for (int jj = 0; jj < 5; jj++)
                            rowd = fmaf(s_G[ii*5+jj], xt[jj], rowd);
                        s2 = fmaf(xt[ii], rowd, s2);
                    }
                    s2 *= (1.0f/32.0f);
                    float var  = fmaf(-mu, mu, s2);
                    float istd = rsqrtf(var + 1e-5f);
                    s_xp[buf][lane] = make_float4(x0*istd, x1*istd, x2*istd, x3*istd);
                    s_mr[buf][lane] = make_float2(rr*istd, mu*istd);
                }
            }
        } else {
            if (i >= 2) {
                const int t = i - 2, buf = t & 1;
                float ge = 0.0f;
                #pragma unroll
                for (int n = 0; n < Nn; n++) {
                    float4 xp = s_xp[buf][n];
                    float2 mr = s_mr[buf][n];
                    float hv = -mr.y;
                    hv = fmaf(xp.x, Wc0, hv);
                    hv = fmaf(xp.y, Wc1, hv);
                    hv = fmaf(xp.z, Wc2, hv);
                    hv = fmaf(xp.w, Wc3, hv);
                    hv = fmaf(mr.x, gcnb, hv);
                    ge += elu(fmaf(hv, lng, lnb));
                }
                ge *= (1.0f / 14.0f);
                g_ge[(b * Tn + t) * Hn + lane] = ge;
            }
        }
        __syncthreads();
    }

    // final esm -> global (symmetric; lane = column)
    if (warp == 0 && lane < Nn) {
        #pragma unroll
        for (int n = 0; n < Nn; n++)
            g_esm[b * (Nn * Nn) + n * Nn + lane] = e[n];
    }
}

// ============ Kernel 2: softmax pool + Jacobi spectrum + classifier ==========
__global__ __launch_bounds__(256)
void tgsm_tail(const float* __restrict__ attn_w, const float* __restrict__ attn_b,
               const float* __restrict__ c1_w, const float* __restrict__ c1_b,
               const float* __restrict__ c2_w, const float* __restrict__ c2_b,
               const float* __restrict__ c3_w, const float* __restrict__ c3_b,
               float* __restrict__ out)
{
    const int b    = blockIdx.x;
    const int tid  = threadIdx.x;
    const int lane = tid & 31;
    const int warp = tid >> 5;

    __shared__ float s_aw[Hn];
    __shared__ float s_w[Tn];
    __shared__ float s_part[8][Hn];
    __shared__ float s_red[2];
    __shared__ float s_A[Nn * Nn];
    __shared__ float s_comb[5 + Hn];
    __shared__ float s_b1[64];

    if (tid < Hn) s_aw[tid] = attn_w[tid];
    if (tid < Nn * Nn) s_A[tid] = g_esm[b * Nn * Nn + tid];
    __syncthreads();

    // attention scores, one t per thread
    const float* gp = g_ge + ((size_t)b * Tn + tid) * Hn;
    float sc = attn_b[0];
    #pragma unroll
    for (int h = 0; h < Hn; h++) sc = fmaf(gp[h], s_aw[h], sc);
    s_w[tid] = sc;
    __syncthreads();

    if (warp == 0) {
        float m = -1e30f;
        #pragma unroll
        for (int k = 0; k < 8; k++) m = fmaxf(m, s_w[lane + k * 32]);
        m = warp_max(m);
        if (lane == 0) s_red[0] = m;
    }
    __syncthreads();
    float M = s_red[0];
    float wt = __expf(sc - M);
    s_w[tid] = wt;
    __syncthreads();

    if (warp == 0) {
        float s = 0.0f;
        #pragma unroll
        for (int k = 0; k < 8; k++) s += s_w[lane + k * 32];
        s = warp_sum(s);
        if (lane == 0) s_red[1] = s;
    }
    // pooled partials: warp w covers t = w*32..w*32+31, lane = channel
    {
        float acc = 0.0f;
        const float* gb = g_ge + ((size_t)b * Tn + warp * 32) * Hn;
        #pragma unroll 8
        for (int j = 0; j < 32; j++)
            acc = fmaf(s_w[warp * 32 + j], gb[j * Hn + lane], acc);
        s_part[warp][lane] = acc;
    }
    __syncthreads();

    if (warp == 0) {
        float pooled = 0.0f;
        #pragma unroll
        for (int w8 = 0; w8 < 8; w8++) pooled += s_part[w8][lane];
        s_comb[5 + lane] = __fdividef(pooled, s_red[1]);

        // cyclic Jacobi eigensolver on s_A (warp-uniform)
        for (int sweep = 0; sweep < 8; sweep++) {
            for (int pp = 0; pp < Nn - 1; pp++) {
                for (int qq = pp + 1; qq < Nn; qq++) {
                    float apq = s_A[pp * Nn + qq];
                    if (fabsf(apq) > 1e-11f) {
                        float app = s_A[pp * Nn + pp];
                        float aqq = s_A[qq * Nn + qq];
                        float theta = 0.5f * __fdividef(aqq - app, apq);
                        float tt = __fdividef(1.0f, fabsf(theta) + sqrtf(fmaf(theta, theta, 1.0f)));
                        if (theta < 0.0f) tt = -tt;
                        float cc  = rsqrtf(fmaf(tt, tt, 1.0f));
                        float ssn = tt * cc;
                        int k = lane;
                        bool act = (k < Nn) && (k != pp) && (k != qq);
                        float akp = 0.f, akq = 0.f;
                        if (act) { akp = s_A[k * Nn + pp]; akq = s_A[k * Nn + qq]; }
                        __syncwarp();
                        if (act) {
                            float nkp = fmaf(cc, akp, -ssn * akq);
                            float nkq = fmaf(ssn, akp,  cc * akq);
                            s_A[k * Nn + pp] = nkp; s_A[pp * Nn + k] = nkp;
                            s_A[k * Nn + qq] = nkq; s_A[qq * Nn + k] = nkq;
                        }
                        if (lane == 0) {
                            s_A[pp * Nn + pp] = fmaf(-tt, apq, app);
                            s_A[qq * Nn + qq] = fmaf( tt, apq, aqq);
                            s_A[pp * Nn + qq] = 0.0f;
                            s_A[qq * Nn + pp] = 0.0f;
                        }
                        __syncwarp();
                    }
                }
            }
        }
        // top-5 eigenvalues ascending via parallel rank
        float ev = (lane < Nn) ? s_A[lane * Nn + lane] : 1e30f;
        int rank = 0;
        #pragma unroll
        for (int j = 0; j < Nn; j++) {
            float evj = s_A[j * Nn + j];
            rank += (evj < ev || (evj == ev && j < lane)) ? 1 : 0;
        }
        if (lane < Nn && rank >= Nn - 5) s_comb[rank - (Nn - 5)] = ev;
    }
    __syncthreads();

    // classifier: 37 -> 64 (elu) -> 32 (elu) -> 2
    if (tid < 64) {
        float a = c1_b[tid];
        #pragma unroll
        for (int i = 0; i < 37; i++)
            a = fmaf(s_comb[i], c1_w[i * 64 + tid], a);
        s_b1[tid] = elu(a);
    }
    __syncthreads();
    if (warp == 0) {
        float a2 = c2_b[lane];
        #pragma unroll
        for (int i = 0; i < 64; i++)
            a2 = fmaf(s_b1[i], c2_w[i * 32 + lane], a2);
        float h2 = elu(a2);
        float r0 = warp_sum(h2 * c3_w[lane * 2 + 0]);
        float r1 = warp_sum(h2 * c3_w[lane * 2 + 1]);
        if (lane == 0) {
            out[b * 2 + 0] = r0 + c3_b[0];
            out[b * 2 + 1] = r1 + c3_b[1];
        }
    }
}

extern "C" void kernel_launch(void* const* d_in, const int* in_sizes, int n_in,
                              void* d_out, int out_size)
{
    const float* ws     = (const float*)d_in[0];
    const float* gate_w = (const float*)d_in[1];
    const float* gate_b = (const float*)d_in[2];
    const float* gcn_w  = (const float*)d_in[3];
    const float* gcn_b  = (const float*)d_in[4];
    const float* ln_g   = (const float*)d_in[5];
    const float* ln_b   = (const float*)d_in[6];
    const float* attn_w = (const float*)d_in[7];
    const float* attn_b = (const float*)d_in[8];
    const float* c1_w   = (const float*)d_in[9];
    const float* c1_b   = (const float*)d_in[10];
    const float* c2_w   = (const float*)d_in[11];
    const float* c2_b   = (const float*)d_in[12];
    const float* c3_w   = (const float*)d_in[13];
    const float* c3_b   = (const float*)d_in[14];
    float* out = (float*)d_out;

    tgsm_scan<<<Bn, 96>>>(ws, gate_w, gate_b, gcn_w, gcn_b, ln_g, ln_b);
    tgsm_tail<<<Bn, 256>>>(attn_w, attn_b, c1_w, c1_b, c2_w, c2_b,
                           c3_w, c3_b, out);
}

// round 7
// speedup vs baseline: 1.2893x; 1.2893x over previous
#include <cuda_runtime.h>
#include <cuda_bf16.h>

// TGSM v7: scan = 4-warp pipeline (P recurrence half-col / B matvec+stats /
// C-even, C-odd apply); tail = pooling + PARALLEL Jacobi + classifier.
// B=1024, T=256, N=14, Fd=4, H=32, K=5, C=2

#define Bn 1024
#define Tn 256
#define Nn 14
#define Hn 32

__device__ float g_ge[Bn * Tn * Hn];
__device__ float g_esm[Bn * Nn * Nn];

__device__ __forceinline__ float warp_sum(float v) {
    v += __shfl_xor_sync(0xffffffffu, v, 16);
    v += __shfl_xor_sync(0xffffffffu, v, 8);
    v += __shfl_xor_sync(0xffffffffu, v, 4);
    v += __shfl_xor_sync(0xffffffffu, v, 2);
    v += __shfl_xor_sync(0xffffffffu, v, 1);
    return v;
}
__device__ __forceinline__ float warp_max(float v) {
    v = fmaxf(v, __shfl_xor_sync(0xffffffffu, v, 16));
    v = fmaxf(v, __shfl_xor_sync(0xffffffffu, v, 8));
    v = fmaxf(v, __shfl_xor_sync(0xffffffffu, v, 4));
    v = fmaxf(v, __shfl_xor_sync(0xffffffffu, v, 2));
    v = fmaxf(v, __shfl_xor_sync(0xffffffffu, v, 1));
    return v;
}
__device__ __forceinline__ float elu(float y) {
    return (y > 0.0f) ? y : (__expf(y) - 1.0f);
}
__device__ __forceinline__ float sigmoid_fast(float x) {
    float th;
    asm("tanh.approx.f32 %0, %1;" : "=f"(th) : "f"(0.5f * x));
    return fmaf(0.5f, th, 0.5f);
}

// ===================== Kernel 1: 4-stage pipelined scan =====================
__global__ __launch_bounds__(128, 7)
void tgsm_scan(const float* __restrict__ ws,
               const float* __restrict__ gate_w, const float* __restrict__ gate_b,
               const float* __restrict__ gcn_w,  const float* __restrict__ gcn_b,
               const float* __restrict__ ln_g,   const float* __restrict__ ln_b)
{
    const int b    = blockIdx.x;
    const int tid  = threadIdx.x;
    const int lane = tid & 31;
    const int warp = tid >> 5;      // 0:P  1:B  2:C-even  3:C-odd
    const int half = lane >> 4;     // 0/1
    const int c    = lane & 15;     // column / node index within half
    const int m0   = 7 * half;

    __shared__ float4 s_nrm[16];          // P internal (within-interval)
    __shared__ float4 s_q[2][16];         // P -> B
    __shared__ float  s_dis[2][16];       // P -> B
    __shared__ float  s_e[2][Nn][16];     // P -> B
    __shared__ float4 s_xp[4][16];        // B -> C
    __shared__ float2 s_mr[4][16];        // B -> C
    __shared__ float  s_G[25];            // Gram of [W;b]
    __shared__ float  s_SWb[5];           // row sums of [W;b]

    // ---- per-warp constants ----
    float gw0 = 0.f, gw1 = 0.f, gbv = 0.f;
    float Wc0 = 0.f, Wc1 = 0.f, Wc2 = 0.f, Wc3 = 0.f, gcnb = 0.f;
    float lng = 0.f, lnb = 0.f;

    if (warp == 0) {
        gw0 = gate_w[0]; gw1 = gate_w[1]; gbv = gate_b[0];
    } else {
        Wc0 = gcn_w[0 * Hn + lane];
        Wc1 = gcn_w[1 * Hn + lane];
        Wc2 = gcn_w[2 * Hn + lane];
        Wc3 = gcn_w[3 * Hn + lane];
        gcnb = gcn_b[lane];
        lng = ln_g[lane]; lnb = ln_b[lane];
        if (warp == 1) {
            float vW[5] = {Wc0, Wc1, Wc2, Wc3, gcnb};
            #pragma unroll
            for (int i2 = 0; i2 < 5; i2++) {
                #pragma unroll
                for (int j2 = i2; j2 < 5; j2++) {
                    float g = warp_sum(vW[i2] * vW[j2]);
                    if (lane == 0) { s_G[i2*5+j2] = g; s_G[j2*5+i2] = g; }
                }
                float sw = warp_sum(vW[i2]);
                if (lane == 0) s_SWb[i2] = sw;
            }
        }
    }

    // P state: half esm column — lane (half,c) holds e[m0+k][c], k=0..6
    float e[7];
    #pragma unroll
    for (int k = 0; k < 7; k++) e[k] = 0.0f;

    // C state: partial ge carried one interval
    float geacc = 0.0f;

    const float4* src = reinterpret_cast<const float4*>(ws) + (size_t)b * Tn * Nn;
    float4 dcur = make_float4(0.f,0.f,0.f,0.f);
    float4 dnxt = make_float4(0.f,0.f,0.f,0.f);
    if (warp == 0 && lane < Nn) dcur = src[lane];

    __syncthreads();   // s_G / s_SWb visible

    for (int i = 0; i < Tn + 3; i++) {
        if (warp == 0) {
            // =========== P: step i ===========
            if (i < Tn) {
                float4 de = dcur;
                if (lane < Nn && i + 1 < Tn) dnxt = src[(i + 1) * Nn + lane];
                if (lane < 16) {
                    float d2 = de.x*de.x + de.y*de.y + de.z*de.z + de.w*de.w;
                    float inv = rsqrtf(fmaxf(d2, 1e-24f));
                    s_nrm[lane] = make_float4(de.x*inv, de.y*inv, de.z*inv, de.w*inv);
                }
                __syncwarp();
                const bool act = (c < Nn);
                float4 nc = s_nrm[c];
                const int buf = i & 1;
                float rs = 0.0f;
                #pragma unroll
                for (int k = 0; k < 7; k++) {
                    int m = m0 + k;
                    float4 nm = s_nrm[m];
                    float dot = nc.x*nm.x;
                    dot = fmaf(nc.y, nm.y, dot);
                    dot = fmaf(nc.z, nm.z, dot);
                    dot = fmaf(nc.w, nm.w, dot);
                    float adj = fmaf(dot, 0.5f, 0.5f);
                    adj = (m == c) ? 0.0f : adj;
                    float ee = e[k];
                    float xg = fmaf(gw0, ee, fmaf(gw1, adj, gbv));
                    float z  = sigmoid_fast(xg);
                    ee = fmaf(z, adj - ee, ee);
                    e[k] = ee;
                    rs += ee;
                    if (act) s_e[buf][m][c] = ee;
                }
                rs += __shfl_xor_sync(0xffffffffu, rs, 16);
                if (lane < Nn) {
                    float dis = rsqrtf(fmaxf(rs + 1.0f, 1e-6f));
                    s_q[buf][lane] = make_float4(de.x*dis, de.y*dis, de.z*dis, de.w*dis);
                    s_dis[buf][lane] = dis;
                }
                dcur = dnxt;
            }
        } else if (warp == 1) {
            // =========== B: step t = i-1 ===========
            const int t = i - 1;
            if (t >= 0 && t < Tn) {
                const int buf = t & 1;
                float4 p = make_float4(0.f,0.f,0.f,0.f);
                float racc = 0.0f;
                #pragma unroll
                for (int k = 0; k < 7; k++) {
                    int m = m0 + k;
                    float em  = s_e[buf][m][c];
                    float4 qm = s_q[buf][m];
                    float dm  = s_dis[buf][m];
                    p.x = fmaf(em, qm.x, p.x);
                    p.y = fmaf(em, qm.y, p.y);
                    p.z = fmaf(em, qm.z, p.z);
                    p.w = fmaf(em, qm.w, p.w);
                    racc = fmaf(em, dm, racc);
                }
                p.x += __shfl_xor_sync(0xffffffffu, p.x, 16);
                p.y += __shfl_xor_sync(0xffffffffu, p.y, 16);
                p.z += __shfl_xor_sync(0xffffffffu, p.z, 16);
                p.w += __shfl_xor_sync(0xffffffffu, p.w, 16);
                racc += __shfl_xor_sync(0xffffffffu, racc, 16);
                if (lane < Nn) {
                    float dis = s_dis[buf][lane];
                    float4 q  = s_q[buf][lane];
                    float rr = dis * (racc + dis);
                    float x0 = (p.x + q.x) * dis;
                    float x1 = (p.y + q.y) * dis;
                    float x2 = (p.z + q.z) * dis;
                    float x3 = (p.w + q.w) * dis;
                    float mu = (x0*s_SWb[0] + x1*s_SWb[1] + x2*s_SWb[2]
                              + x3*s_SWb[3] + rr*s_SWb[4]) * (1.0f/32.0f);
                    float xt[5] = {x0, x1, x2, x3, rr};
                    float s2 = 0.0f;
                    #pragma unroll
                    for (int ii = 0; ii < 5; ii++) {
                        float rowd = 0.0f;
                        #pragma unroll
                        for (int jj = 0; jj < 5; jj++)
                            rowd = fmaf(s_G[ii*5+jj], xt[jj], rowd);
                        s2 = fmaf(xt[ii], rowd, s2);
                    }
                    s2 *= (1.0f/32.0f);
                    float var  = fmaf(-mu, mu, s2);
                    float istd = rsqrtf(var + 1e-5f);
                    s_xp[t & 3][lane] = make_float4(x0*istd, x1*istd, x2*istd, x3*istd);
                    s_mr[t & 3][lane] = make_float2(rr*istd, mu*istd);
                }
            }
        } else {
            // =========== C: warp2 = even steps, warp3 = odd steps ===========
            const int wpar = warp - 2;
            const int ts = i - 2;     // start phase: nodes 0-6
            if (ts >= 0 && ts < Tn && (ts & 1) == wpar) {
                const int sb = ts & 3;
                float acc = 0.0f;
                #pragma unroll
                for (int n = 0; n < 7; n++) {
                    float4 xp = s_xp[sb][n];
                    float2 mr = s_mr[sb][n];
                    float hv = -mr.y;
                    hv = fmaf(xp.x, Wc0, hv);
                    hv = fmaf(xp.y, Wc1, hv);
                    hv = fmaf(xp.z, Wc2, hv);
                    hv = fmaf(xp.w, Wc3, hv);
                    hv = fmaf(mr.x, gcnb, hv);
                    acc += elu(fmaf(hv, lng, lnb));
                }
                geacc = acc;
            }
            const int tf = i - 3;     // finish phase: nodes 7-13 + store
            if (tf >= 0 && tf < Tn && (tf & 1) == wpar) {
                const int sb = tf & 3;
                float acc = geacc;
                #pragma unroll
                for (int n = 7; n < Nn; n++) {
                    float4 xp = s_xp[sb][n];
                    float2 mr = s_mr[sb][n];
                    float hv = -mr.y;
                    hv = fmaf(xp.x, Wc0, hv);
                    hv = fmaf(xp.y, Wc1, hv);
                    hv = fmaf(xp.z, Wc2, hv);
                    hv = fmaf(xp.w, Wc3, hv);
                    hv = fmaf(mr.x, gcnb, hv);
                    acc += elu(fmaf(hv, lng, lnb));
                }
                g_ge[((size_t)b * Tn + tf) * Hn + lane] = acc * (1.0f / 14.0f);
            }
        }
        __syncthreads();
    }

    // final esm -> global (lane (half,c) holds rows m0..m0+6 of column c)
    if (warp == 0 && c < Nn) {
        #pragma unroll
        for (int k = 0; k < 7; k++)
            g_esm[b * (Nn * Nn) + (m0 + k) * Nn + c] = e[k];
    }
}

// ====== Kernel 2: softmax pool + PARALLEL Jacobi spectrum + classifier ======
__global__ __launch_bounds__(256)
void tgsm_tail(const float* __restrict__ attn_w, const float* __restrict__ attn_b,
               const float* __restrict__ c1_w, const float* __restrict__ c1_b,
               const float* __restrict__ c2_w, const float* __restrict__ c2_b,
               const float* __restrict__ c3_w, const float* __restrict__ c3_b,
               float* __restrict__ out)
{
    const int b    = blockIdx.x;
    const int tid  = threadIdx.x;
    const int lane = tid & 31;
    const int warp = tid >> 5;

    __shared__ float  s_aw[Hn];
    __shared__ float  s_w[Tn];
    __shared__ float  s_part[8][Hn];
    __shared__ float  s_red[2];
    __shared__ float  s_A[Nn * Nn];
    __shared__ float2 s_cs[7];
    __shared__ int2   s_pq[7];
    __shared__ float  s_comb[5 + Hn];
    __shared__ float  s_b1[64];

    if (tid < Hn) s_aw[tid] = attn_w[tid];
    if (tid < Nn * Nn) s_A[tid] = g_esm[b * Nn * Nn + tid];
    __syncthreads();

    // attention scores, one t per thread
    const float* gp = g_ge + ((size_t)b * Tn + tid) * Hn;
    float sc = attn_b[0];
    #pragma unroll
    for (int h = 0; h < Hn; h++) sc = fmaf(gp[h], s_aw[h], sc);
    s_w[tid] = sc;
    __syncthreads();

    if (warp == 0) {
        float m = -1e30f;
        #pragma unroll
        for (int k = 0; k < 8; k++) m = fmaxf(m, s_w[lane + k * 32]);
        m = warp_max(m);
        if (lane == 0) s_red[0] = m;
    }
    __syncthreads();
    float M = s_red[0];
    float wt = __expf(sc - M);
    s_w[tid] = wt;
    __syncthreads();

    if (warp == 0) {
        float s = 0.0f;
        #pragma unroll
        for (int k = 0; k < 8; k++) s += s_w[lane + k * 32];
        s = warp_sum(s);
        if (lane == 0) s_red[1] = s;
    }
    // pooled partials: warp w covers t = w*32..w*32+31, lane = channel
    {
        float acc = 0.0f;
        const float* gb = g_ge + ((size_t)b * Tn + warp * 32) * Hn;
        #pragma unroll 8
        for (int j = 0; j < 32; j++)
            acc = fmaf(s_w[warp * 32 + j], gb[j * Hn + lane], acc);
        s_part[warp][lane] = acc;
    }
    __syncthreads();

    if (warp == 0) {
        float pooled = 0.0f;
        #pragma unroll
        for (int w8 = 0; w8 < 8; w8++) pooled += s_part[w8][lane];
        s_comb[5 + lane] = __fdividef(pooled, s_red[1]);

        // ---- PARALLEL cyclic Jacobi: 7 disjoint rotations per round ----
        for (int sweep = 0; sweep < 8; sweep++) {
            for (int r = 0; r < 13; r++) {
                if (lane < 7) {
                    int pj = (lane == 0) ? 0 : 1 + (lane - 1 + r) % 13;
                    int qj = 1 + (12 - lane + r) % 13;
                    float apq = s_A[pj * Nn + qj];
                    float app = s_A[pj * Nn + pj];
                    float aqq = s_A[qj * Nn + qj];
                    float ap  = fabsf(apq);
                    float den = (ap > 1e-20f) ? apq : 1.0f;
                    float theta = __fdividef(0.5f * (aqq - app), den);
                    float tt = __fdividef(1.0f, fabsf(theta) + sqrtf(fmaf(theta, theta, 1.0f)));
                    tt = (theta < 0.0f) ? -tt : tt;
                    tt = (ap > 1e-20f) ? tt : 0.0f;
                    float cc = rsqrtf(fmaf(tt, tt, 1.0f));
                    s_cs[lane] = make_float2(cc, tt * cc);
                    s_pq[lane] = make_int2(pj, qj);
                }
                __syncwarp();
                // column pass: mix columns (p,q) for every row
                #pragma unroll
                for (int idx = lane; idx < 98; idx += 32) {
                    int row = idx / 7;
                    int kk  = idx - row * 7;
                    float2 cs = s_cs[kk];
                    int2   pq = s_pq[kk];
                    float ap_ = s_A[row * Nn + pq.x];
                    float aq_ = s_A[row * Nn + pq.y];
                    s_A[row * Nn + pq.x] = cs.x * ap_ - cs.y * aq_;
                    s_A[row * Nn + pq.y] = fmaf(cs.y, ap_, cs.x * aq_);
                }
                __syncwarp();
                // row pass: mix rows (p,q) for every column
                #pragma unroll
                for (int idx = lane; idx < 98; idx += 32) {
                    int col = idx / 7;
                    int kk  = idx - col * 7;
                    float2 cs = s_cs[kk];
                    int2   pq = s_pq[kk];
                    float pa = s_A[pq.x * Nn + col];
                    float qa = s_A[pq.y * Nn + col];
                    s_A[pq.x * Nn + col] = cs.x * pa - cs.y * qa;
                    s_A[pq.y * Nn + col] = fmaf(cs.y, pa, cs.x * qa);
                }
                __syncwarp();
            }
        }
        // top-5 eigenvalues ascending via parallel rank
        float ev = (lane < Nn) ? s_A[lane * Nn + lane] : 1e30f;
        int rank = 0;
        #pragma unroll
        for (int j = 0; j < Nn; j++) {
            float evj = s_A[j * Nn + j];
            rank += (evj < ev || (evj == ev && j < lane)) ? 1 : 0;
        }
        if (lane < Nn && rank >= Nn - 5) s_comb[rank - (Nn - 5)] = ev;
    }
    __syncthreads();

    // classifier: 37 -> 64 (elu) -> 32 (elu) -> 2
    if (tid < 64) {
        float a = c1_b[tid];
        #pragma unroll
        for (int i = 0; i < 37; i++)
            a = fmaf(s_comb[i], c1_w[i * 64 + tid], a);
        s_b1[tid] = elu(a);
    }
    __syncthreads();
    if (warp == 0) {
        float a2 = c2_b[lane];
        #pragma unroll
        for (int i = 0; i < 64; i++)
            a2 = fmaf(s_b1[i], c2_w[i * 32 + lane], a2);
        float h2 = elu(a2);
        float r0 = warp_sum(h2 * c3_w[lane * 2 + 0]);
        float r1 = warp_sum(h2 * c3_w[lane * 2 + 1]);
        if (lane == 0) {
            out[b * 2 + 0] = r0 + c3_b[0];
            out[b * 2 + 1] = r1 + c3_b[1];
        }
    }
}

extern "C" void kernel_launch(void* const* d_in, const int* in_sizes, int n_in,
                              void* d_out, int out_size)
{
    const float* ws     = (const float*)d_in[0];
    const float* gate_w = (const float*)d_in[1];
    const float* gate_b = (const float*)d_in[2];
    const float* gcn_w  = (const float*)d_in[3];
    const float* gcn_b  = (const float*)d_in[4];
    const float* ln_g   = (const float*)d_in[5];
    const float* ln_b   = (const float*)d_in[6];
    const float* attn_w = (const float*)d_in[7];
    const float* attn_b = (const float*)d_in[8];
    const float* c1_w   = (const float*)d_in[9];
    const float* c1_b   = (const float*)d_in[10];
    const float* c2_w   = (const float*)d_in[11];
    const float* c2_b   = (const float*)d_in[12];
    const float* c3_w   = (const float*)d_in[13];
    const float* c3_b   = (const float*)d_in[14];
    float* out = (float*)d_out;

    tgsm_scan<<<Bn, 128>>>(ws, gate_w, gate_b, gcn_w, gcn_b, ln_g, ln_b);
    tgsm_tail<<<Bn, 256>>>(attn_w, attn_b, c1_w, c1_b, c2_w, c2_b,
                           c3_w, c3_b, out);
}

// round 8
// speedup vs baseline: 1.4887x; 1.1547x over previous
#include <cuda_runtime.h>
#include <cuda_bf16.h>

// TGSM v8: v7 scan + per-block role rotation (SMSP balance) + scores in scan;
// tail = coalesced softmax pool + block-parallel Jacobi + classifier.
// B=1024, T=256, N=14, Fd=4, H=32, K=5, C=2

#define Bn 1024
#define Tn 256
#define Nn 14
#define Hn 32

__device__ float g_ge[Bn * Tn * Hn];
__device__ float g_sc[Bn * Tn];
__device__ float g_esm[Bn * Nn * Nn];

__device__ __forceinline__ float warp_sum(float v) {
    v += __shfl_xor_sync(0xffffffffu, v, 16);
    v += __shfl_xor_sync(0xffffffffu, v, 8);
    v += __shfl_xor_sync(0xffffffffu, v, 4);
    v += __shfl_xor_sync(0xffffffffu, v, 2);
    v += __shfl_xor_sync(0xffffffffu, v, 1);
    return v;
}
__device__ __forceinline__ float warp_max(float v) {
    v = fmaxf(v, __shfl_xor_sync(0xffffffffu, v, 16));
    v = fmaxf(v, __shfl_xor_sync(0xffffffffu, v, 8));
    v = fmaxf(v, __shfl_xor_sync(0xffffffffu, v, 4));
    v = fmaxf(v, __shfl_xor_sync(0xffffffffu, v, 2));
    v = fmaxf(v, __shfl_xor_sync(0xffffffffu, v, 1));
    return v;
}
__device__ __forceinline__ float elu(float y) {
    return (y > 0.0f) ? y : (__expf(y) - 1.0f);
}
__device__ __forceinline__ float sigmoid_fast(float x) {
    float th;
    asm("tanh.approx.f32 %0, %1;" : "=f"(th) : "f"(0.5f * x));
    return fmaf(0.5f, th, 0.5f);
}

// ===================== Kernel 1: 4-stage pipelined scan =====================
__global__ __launch_bounds__(128, 7)
void tgsm_scan(const float* __restrict__ ws,
               const float* __restrict__ gate_w, const float* __restrict__ gate_b,
               const float* __restrict__ gcn_w,  const float* __restrict__ gcn_b,
               const float* __restrict__ ln_g,   const float* __restrict__ ln_b,
               const float* __restrict__ attn_w, const float* __restrict__ attn_b)
{
    const int b    = blockIdx.x;
    const int tid  = threadIdx.x;
    const int lane = tid & 31;
    const int warp = tid >> 5;
    const int role = (warp + b) & 3;   // 0:P  1:B  2:C-even  3:C-odd  (SMSP-balanced)
    const int half = lane >> 4;
    const int c    = lane & 15;
    const int m0   = 7 * half;

    __shared__ float4 s_nrm[16];
    __shared__ float4 s_q[2][16];
    __shared__ float  s_dis[2][16];
    __shared__ float  s_e[2][Nn][16];
    __shared__ float4 s_xp[4][16];
    __shared__ float2 s_mr[4][16];
    __shared__ float  s_G[25];
    __shared__ float  s_SWb[5];

    // ---- per-role constants ----
    float gw0 = 0.f, gw1 = 0.f, gbv = 0.f;
    float Wc0 = 0.f, Wc1 = 0.f, Wc2 = 0.f, Wc3 = 0.f, gcnb = 0.f;
    float lng = 0.f, lnb = 0.f, awv = 0.f, attnb = 0.f;

    if (role == 0) {
        gw0 = gate_w[0]; gw1 = gate_w[1]; gbv = gate_b[0];
    } else {
        Wc0 = gcn_w[0 * Hn + lane];
        Wc1 = gcn_w[1 * Hn + lane];
        Wc2 = gcn_w[2 * Hn + lane];
        Wc3 = gcn_w[3 * Hn + lane];
        gcnb = gcn_b[lane];
        lng = ln_g[lane]; lnb = ln_b[lane];
        awv = attn_w[lane]; attnb = attn_b[0];
        if (role == 1) {
            float vW[5] = {Wc0, Wc1, Wc2, Wc3, gcnb};
            #pragma unroll
            for (int i2 = 0; i2 < 5; i2++) {
                #pragma unroll
                for (int j2 = i2; j2 < 5; j2++) {
                    float g = warp_sum(vW[i2] * vW[j2]);
                    if (lane == 0) { s_G[i2*5+j2] = g; s_G[j2*5+i2] = g; }
                }
                float sw = warp_sum(vW[i2]);
                if (lane == 0) s_SWb[i2] = sw;
            }
        }
    }

    // P state: half esm column — lane (half,c) holds e[m0+k][c], k=0..6
    float e[7];
    #pragma unroll
    for (int k = 0; k < 7; k++) e[k] = 0.0f;

    float geacc = 0.0f;   // C state

    const float4* src = reinterpret_cast<const float4*>(ws) + (size_t)b * Tn * Nn;
    float4 dcur = make_float4(0.f,0.f,0.f,0.f);
    float4 dnxt = make_float4(0.f,0.f,0.f,0.f);
    if (role == 0 && lane < Nn) dcur = src[lane];

    __syncthreads();   // s_G / s_SWb visible

    for (int i = 0; i < Tn + 3; i++) {
        if (role == 0) {
            // =========== P: step i ===========
            if (i < Tn) {
                float4 de = dcur;
                if (lane < Nn && i + 1 < Tn) dnxt = src[(i + 1) * Nn + lane];
                if (lane < 16) {
                    float d2 = de.x*de.x + de.y*de.y + de.z*de.z + de.w*de.w;
                    float inv = rsqrtf(fmaxf(d2, 1e-24f));
                    s_nrm[lane] = make_float4(de.x*inv, de.y*inv, de.z*inv, de.w*inv);
                }
                __syncwarp();
                const bool act = (c < Nn);
                float4 nc = s_nrm[c];
                const int buf = i & 1;
                float rs = 0.0f;
                #pragma unroll
                for (int k = 0; k < 7; k++) {
                    int m = m0 + k;
                    float4 nm = s_nrm[m];
                    float dot = nc.x*nm.x;
                    dot = fmaf(nc.y, nm.y, dot);
                    dot = fmaf(nc.z, nm.z, dot);
                    dot = fmaf(nc.w, nm.w, dot);
                    float adj = fmaf(dot, 0.5f, 0.5f);
                    adj = (m == c) ? 0.0f : adj;
                    float ee = e[k];
                    float xg = fmaf(gw0, ee, fmaf(gw1, adj, gbv));
                    float z  = sigmoid_fast(xg);
                    ee = fmaf(z, adj - ee, ee);
                    e[k] = ee;
                    rs += ee;
                    if (act) s_e[buf][m][c] = ee;
                }
                rs += __shfl_xor_sync(0xffffffffu, rs, 16);
                if (lane < Nn) {
                    float dis = rsqrtf(fmaxf(rs + 1.0f, 1e-6f));
                    s_q[buf][lane] = make_float4(de.x*dis, de.y*dis, de.z*dis, de.w*dis);
                    s_dis[buf][lane] = dis;
                }
                dcur = dnxt;
            }
        } else if (role == 1) {
            // =========== B: step t = i-1 ===========
            const int t = i - 1;
            if (t >= 0 && t < Tn) {
                const int buf = t & 1;
                float4 p = make_float4(0.f,0.f,0.f,0.f);
                float racc = 0.0f;
                #pragma unroll
                for (int k = 0; k < 7; k++) {
                    int m = m0 + k;
                    float em  = s_e[buf][m][c];
                    float4 qm = s_q[buf][m];
                    float dm  = s_dis[buf][m];
                    p.x = fmaf(em, qm.x, p.x);
                    p.y = fmaf(em, qm.y, p.y);
                    p.z = fmaf(em, qm.z, p.z);
                    p.w = fmaf(em, qm.w, p.w);
                    racc = fmaf(em, dm, racc);
                }
                p.x += __shfl_xor_sync(0xffffffffu, p.x, 16);
                p.y += __shfl_xor_sync(0xffffffffu, p.y, 16);
                p.z += __shfl_xor_sync(0xffffffffu, p.z, 16);
                p.w += __shfl_xor_sync(0xffffffffu, p.w, 16);
                racc += __shfl_xor_sync(0xffffffffu, racc, 16);
                if (lane < Nn) {
                    float dis = s_dis[buf][lane];
                    float4 q  = s_q[buf][lane];
                    float rr = dis * (racc + dis);
                    float x0 = (p.x + q.x) * dis;
                    float x1 = (p.y + q.y) * dis;
                    float x2 = (p.z + q.z) * dis;
                    float x3 = (p.w + q.w) * dis;
                    float mu = (x0*s_SWb[0] + x1*s_SWb[1] + x2*s_SWb[2]
                              + x3*s_SWb[3] + rr*s_SWb[4]) * (1.0f/32.0f);
                    float xt[5] = {x0, x1, x2, x3, rr};
                    float s2 = 0.0f;
                    #pragma unroll
                    for (int ii = 0; ii < 5; ii++) {
                        float rowd = 0.0f;
                        #pragma unroll
                        for (int jj = 0; jj < 5; jj++)
                            rowd = fmaf(s_G[ii*5+jj], xt[jj], rowd);
                        s2 = fmaf(xt[ii], rowd, s2);
                    }
                    s2 *= (1.0f/32.0f);
                    float var  = fmaf(-mu, mu, s2);
                    float istd = rsqrtf(var + 1e-5f);
                    s_xp[t & 3][lane] = make_float4(x0*istd, x1*istd, x2*istd, x3*istd);
                    s_mr[t & 3][lane] = make_float2(rr*istd, mu*istd);
                }
            }
        } else {
            // =========== C: role2 = even steps, role3 = odd steps ===========
            const int wpar = role - 2;
            const int ts = i - 2;     // start phase: nodes 0-6
            if (ts >= 0 && ts < Tn && (ts & 1) == wpar) {
                const int sb = ts & 3;
                float acc = 0.0f;
                #pragma unroll
                for (int n = 0; n < 7; n++) {
                    float4 xp = s_xp[sb][n];
                    float2 mr = s_mr[sb][n];
                    float hv = -mr.y;
                    hv = fmaf(xp.x, Wc0, hv);
                    hv = fmaf(xp.y, Wc1, hv);
                    hv = fmaf(xp.z, Wc2, hv);
                    hv = fmaf(xp.w, Wc3, hv);
                    hv = fmaf(mr.x, gcnb, hv);
                    acc += elu(fmaf(hv, lng, lnb));
                }
                geacc = acc;
            }
            const int tf = i - 3;     // finish phase: nodes 7-13 + score + store
            if (tf >= 0 && tf < Tn && (tf & 1) == wpar) {
                const int sb = tf & 3;
                float acc = geacc;
                #pragma unroll
                for (int n = 7; n < Nn; n++) {
                    float4 xp = s_xp[sb][n];
                    float2 mr = s_mr[sb][n];
                    float hv = -mr.y;
                    hv = fmaf(xp.x, Wc0, hv);
                    hv = fmaf(xp.y, Wc1, hv);
                    hv = fmaf(xp.z, Wc2, hv);
                    hv = fmaf(xp.w, Wc3, hv);
                    hv = fmaf(mr.x, gcnb, hv);
                    acc += elu(fmaf(hv, lng, lnb));
                }
                float ge = acc * (1.0f / 14.0f);
                g_ge[((size_t)b * Tn + tf) * Hn + lane] = ge;
                float sc = warp_sum(ge * awv) + attnb;
                if (lane == 0) g_sc[b * Tn + tf] = sc;
            }
        }
        __syncthreads();
    }

    // final esm -> global (lane (half,c) holds rows m0..m0+6 of column c)
    if (role == 0 && c < Nn) {
        #pragma unroll
        for (int k = 0; k < 7; k++)
            g_esm[b * (Nn * Nn) + (m0 + k) * Nn + c] = e[k];
    }
}

// ====== Kernel 2: softmax pool + block-parallel Jacobi + classifier ======
__global__ __launch_bounds__(256)
void tgsm_tail(const float* __restrict__ c1_w, const float* __restrict__ c1_b,
               const float* __restrict__ c2_w, const float* __restrict__ c2_b,
               const float* __restrict__ c3_w, const float* __restrict__ c3_b,
               float* __restrict__ out)
{
    const int b    = blockIdx.x;
    const int tid  = threadIdx.x;
    const int lane = tid & 31;
    const int warp = tid >> 5;

    __shared__ float  s_w[Tn];
    __shared__ float  s_part[8][Hn];
    __shared__ float  s_red[2];
    __shared__ float  s_A[Nn * Nn];
    __shared__ float2 s_cs[7];
    __shared__ int2   s_pq[7];
    __shared__ float  s_comb[5 + Hn];
    __shared__ float  s_b1[64];

    // coalesced score load + esm load
    float sc = g_sc[b * Tn + tid];
    s_w[tid] = sc;
    if (tid < Nn * Nn) s_A[tid] = g_esm[b * Nn * Nn + tid];
    __syncthreads();

    if (warp == 0) {
        float m = -1e30f;
        #pragma unroll
        for (int k = 0; k < 8; k++) m = fmaxf(m, s_w[lane + k * 32]);
        m = warp_max(m);
        if (lane == 0) s_red[0] = m;
    }
    __syncthreads();
    float wt = __expf(sc - s_red[0]);
    s_w[tid] = wt;
    __syncthreads();

    if (warp == 0) {
        float s = 0.0f;
        #pragma unroll
        for (int k = 0; k < 8; k++) s += s_w[lane + k * 32];
        s = warp_sum(s);
        if (lane == 0) s_red[1] = s;
    }
    // pooled partials: warp w covers t = w*32..w*32+31, lane = channel (coalesced)
    {
        float acc = 0.0f;
        const float* gb = g_ge + ((size_t)b * Tn + warp * 32) * Hn;
        #pragma unroll 8
        for (int j = 0; j < 32; j++)
            acc = fmaf(s_w[warp * 32 + j], gb[j * Hn + lane], acc);
        s_part[warp][lane] = acc;
    }
    __syncthreads();

    if (warp == 0) {
        float pooled = 0.0f;
        #pragma unroll
        for (int w8 = 0; w8 < 8; w8++) pooled += s_part[w8][lane];
        s_comb[5 + lane] = __fdividef(pooled, s_red[1]);
    }

    // ---- block-parallel cyclic Jacobi: 7 disjoint rotations / round ----
    for (int sweep = 0; sweep < 8; sweep++) {
        for (int r = 0; r < 13; r++) {
            if (tid < 7) {
                int pj = (tid == 0) ? 0 : 1 + (tid - 1 + r) % 13;
                int qj = 1 + (12 - tid + r) % 13;
                float apq = s_A[pj * Nn + qj];
                float app = s_A[pj * Nn + pj];
                float aqq = s_A[qj * Nn + qj];
                float ap  = fabsf(apq);
                float den = (ap > 1e-20f) ? apq : 1.0f;
                float theta = __fdividef(0.5f * (aqq - app), den);
                float tt = __fdividef(1.0f, fabsf(theta) + sqrtf(fmaf(theta, theta, 1.0f)));
                tt = (theta < 0.0f) ? -tt : tt;
                tt = (ap > 1e-20f) ? tt : 0.0f;
                float cc = rsqrtf(fmaf(tt, tt, 1.0f));
                s_cs[tid] = make_float2(cc, tt * cc);
                s_pq[tid] = make_int2(pj, qj);
            }
            __syncthreads();
            if (tid < 98) {   // column pass
                int row = tid / 7;
                int kk  = tid - row * 7;
                float2 cs = s_cs[kk];
                int2   pq = s_pq[kk];
                float ap_ = s_A[row * Nn + pq.x];
                float aq_ = s_A[row * Nn + pq.y];
                s_A[row * Nn + pq.x] = cs.x * ap_ - cs.y * aq_;
                s_A[row * Nn + pq.y] = fmaf(cs.y, ap_, cs.x * aq_);
            }
            __syncthreads();
            if (tid < 98) {   // row pass
                int col = tid / 7;
                int kk  = tid - col * 7;
                float2 cs = s_cs[kk];
                int2   pq = s_pq[kk];
                float pa = s_A[pq.x * Nn + col];
                float qa = s_A[pq.y * Nn + col];
                s_A[pq.x * Nn + col] = cs.x * pa - cs.y * qa;
                s_A[pq.y * Nn + col] = fmaf(cs.y, pa, cs.x * qa);
            }
            __syncthreads();
        }
    }

    // top-5 eigenvalues ascending via parallel rank (warp 0)
    if (warp == 0) {
        float ev = (lane < Nn) ? s_A[lane * Nn + lane] : 1e30f;
        int rank = 0;
        #pragma unroll
        for (int j = 0; j < Nn; j++) {
            float evj = s_A[j * Nn + j];
            rank += (evj < ev || (evj == ev && j < lane)) ? 1 : 0;
        }
        if (lane < Nn && rank >= Nn - 5) s_comb[rank - (Nn - 5)] = ev;
    }
    __syncthreads();

    // classifier: 37 -> 64 (elu) -> 32 (elu) -> 2
    if (tid < 64) {
        float a = c1_b[tid];
        #pragma unroll
        for (int i = 0; i < 37; i++)
            a = fmaf(s_comb[i], c1_w[i * 64 + tid], a);
        s_b1[tid] = elu(a);
    }
    __syncthreads();
    if (warp == 0) {
        float a2 = c2_b[lane];
        #pragma unroll
        for (int i = 0; i < 64; i++)
            a2 = fmaf(s_b1[i], c2_w[i * 32 + lane], a2);
        float h2 = elu(a2);
        float r0 = warp_sum(h2 * c3_w[lane * 2 + 0]);
        float r1 = warp_sum(h2 * c3_w[lane * 2 + 1]);
        if (lane == 0) {
            out[b * 2 + 0] = r0 + c3_b[0];
            out[b * 2 + 1] = r1 + c3_b[1];
        }
    }
}

extern "C" void kernel_launch(void* const* d_in, const int* in_sizes, int n_in,
                              void* d_out, int out_size)
{
    const float* ws     = (const float*)d_in[0];
    const float* gate_w = (const float*)d_in[1];
    const float* gate_b = (const float*)d_in[2];
    const float* gcn_w  = (const float*)d_in[3];
    const float* gcn_b  = (const float*)d_in[4];
    const float* ln_g   = (const float*)d_in[5];
    const float* ln_b   = (const float*)d_in[6];
    const float* attn_w = (const float*)d_in[7];
    const float* attn_b = (const float*)d_in[8];
    const float* c1_w   = (const float*)d_in[9];
    const float* c1_b   = (const float*)d_in[10];
    const float* c2_w   = (const float*)d_in[11];
    const float* c2_b   = (const float*)d_in[12];
    const float* c3_w   = (const float*)d_in[13];
    const float* c3_b   = (const float*)d_in[14];
    float* out = (float*)d_out;

    tgsm_scan<<<Bn, 128>>>(ws, gate_w, gate_b, gcn_w, gcn_b, ln_g, ln_b,
                           attn_w, attn_b);
    tgsm_tail<<<Bn, 256>>>(c1_w, c1_b, c2_w, c2_b, c3_w, c3_b, out);
}

// round 9
// speedup vs baseline: 1.6441x; 1.1044x over previous
#include <cuda_runtime.h>
#include <cuda_bf16.h>

// TGSM v9: single fused kernel. 4-warp pipelined scan (role-rotated), then
// inline tail: P-warp does Jacobi (syncwarp) WHILE other 3 warps do
// softmax pooling (named barrier), then classifier. Only g_ge stays global.
// B=1024, T=256, N=14, Fd=4, H=32, K=5, C=2

#define Bn 1024
#define Tn 256
#define Nn 14
#define Hn 32

__device__ float g_ge[Bn * Tn * Hn];

__device__ __forceinline__ float warp_sum(float v) {
    v += __shfl_xor_sync(0xffffffffu, v, 16);
    v += __shfl_xor_sync(0xffffffffu, v, 8);
    v += __shfl_xor_sync(0xffffffffu, v, 4);
    v += __shfl_xor_sync(0xffffffffu, v, 2);
    v += __shfl_xor_sync(0xffffffffu, v, 1);
    return v;
}
__device__ __forceinline__ float warp_max(float v) {
    v = fmaxf(v, __shfl_xor_sync(0xffffffffu, v, 16));
    v = fmaxf(v, __shfl_xor_sync(0xffffffffu, v, 8));
    v = fmaxf(v, __shfl_xor_sync(0xffffffffu, v, 4));
    v = fmaxf(v, __shfl_xor_sync(0xffffffffu, v, 2));
    v = fmaxf(v, __shfl_xor_sync(0xffffffffu, v, 1));
    return v;
}
__device__ __forceinline__ float elu(float y) {
    return (y > 0.0f) ? y : (__expf(y) - 1.0f);
}
__device__ __forceinline__ float sigmoid_fast(float x) {
    float th;
    asm("tanh.approx.f32 %0, %1;" : "=f"(th) : "f"(0.5f * x));
    return fmaf(0.5f, th, 0.5f);
}

__global__ __launch_bounds__(128, 7)
void tgsm_fused(const float* __restrict__ ws,
                const float* __restrict__ gate_w, const float* __restrict__ gate_b,
                const float* __restrict__ gcn_w,  const float* __restrict__ gcn_b,
                const float* __restrict__ ln_g,   const float* __restrict__ ln_b,
                const float* __restrict__ attn_w, const float* __restrict__ attn_b,
                const float* __restrict__ c1_w,   const float* __restrict__ c1_b,
                const float* __restrict__ c2_w,   const float* __restrict__ c2_b,
                const float* __restrict__ c3_w,   const float* __restrict__ c3_b,
                float* __restrict__ out)
{
    const int b    = blockIdx.x;
    const int tid  = threadIdx.x;
    const int lane = tid & 31;
    const int warp = tid >> 5;
    const int role = (warp + b) & 3;   // 0:P  1:B  2:C-even  3:C-odd
    const int half = lane >> 4;
    const int c    = lane & 15;
    const int m0   = 7 * half;

    __shared__ float4 s_nrm[16];
    __shared__ float4 s_q[2][16];
    __shared__ float  s_dis[2][16];
    __shared__ float  s_e[2][Nn][16];
    __shared__ float4 s_xp[4][16];
    __shared__ float2 s_mr[4][16];
    __shared__ float  s_G[25];
    __shared__ float  s_SWb[5];
    __shared__ float  s_sc[Tn];        // attention scores
    __shared__ float  s_w[Tn];         // softmax weights
    __shared__ float  s_A[Nn * Nn];    // esm for Jacobi
    __shared__ float2 s_cs[7];
    __shared__ int2   s_pq[7];
    __shared__ float  s_part[3][Hn];
    __shared__ float  s_comb[5 + Hn];
    __shared__ float  s_b1[64];

    // ---- per-role constants ----
    float gw0 = 0.f, gw1 = 0.f, gbv = 0.f;
    float Wc0 = 0.f, Wc1 = 0.f, Wc2 = 0.f, Wc3 = 0.f, gcnb = 0.f;
    float lng = 0.f, lnb = 0.f, awv = 0.f, attnb = 0.f;

    if (role == 0) {
        gw0 = gate_w[0]; gw1 = gate_w[1]; gbv = gate_b[0];
    } else {
        Wc0 = gcn_w[0 * Hn + lane];
        Wc1 = gcn_w[1 * Hn + lane];
        Wc2 = gcn_w[2 * Hn + lane];
        Wc3 = gcn_w[3 * Hn + lane];
        gcnb = gcn_b[lane];
        lng = ln_g[lane]; lnb = ln_b[lane];
        awv = attn_w[lane]; attnb = attn_b[0];
        if (role == 1) {
            float vW[5] = {Wc0, Wc1, Wc2, Wc3, gcnb};
            #pragma unroll
            for (int i2 = 0; i2 < 5; i2++) {
                #pragma unroll
                for (int j2 = i2; j2 < 5; j2++) {
                    float g = warp_sum(vW[i2] * vW[j2]);
                    if (lane == 0) { s_G[i2*5+j2] = g; s_G[j2*5+i2] = g; }
                }
                float sw = warp_sum(vW[i2]);
                if (lane == 0) s_SWb[i2] = sw;
            }
        }
    }

    // P state: half esm column — lane (half,c) holds e[m0+k][c], k=0..6
    float e[7];
    #pragma unroll
    for (int k = 0; k < 7; k++) e[k] = 0.0f;

    float geacc = 0.0f;   // C state

    const float4* src = reinterpret_cast<const float4*>(ws) + (size_t)b * Tn * Nn;
    float4 dcur = make_float4(0.f,0.f,0.f,0.f);
    float4 dnxt = make_float4(0.f,0.f,0.f,0.f);
    if (role == 0 && lane < Nn) dcur = src[lane];

    __syncthreads();   // s_G / s_SWb visible

    // ======================= pipelined temporal scan =======================
    for (int i = 0; i < Tn + 3; i++) {
        if (role == 0) {
            if (i < Tn) {
                float4 de = dcur;
                if (lane < Nn && i + 1 < Tn) dnxt = src[(i + 1) * Nn + lane];
                if (lane < 16) {
                    float d2 = de.x*de.x + de.y*de.y + de.z*de.z + de.w*de.w;
                    float inv = rsqrtf(fmaxf(d2, 1e-24f));
                    s_nrm[lane] = make_float4(de.x*inv, de.y*inv, de.z*inv, de.w*inv);
                }
                __syncwarp();
                const bool act = (c < Nn);
                float4 nc = s_nrm[c];
                const int buf = i & 1;
                float rs = 0.0f;
                #pragma unroll
                for (int k = 0; k < 7; k++) {
                    int m = m0 + k;
                    float4 nm = s_nrm[m];
                    float dot = nc.x*nm.x;
                    dot = fmaf(nc.y, nm.y, dot);
                    dot = fmaf(nc.z, nm.z, dot);
                    dot = fmaf(nc.w, nm.w, dot);
                    float adj = fmaf(dot, 0.5f, 0.5f);
                    adj = (m == c) ? 0.0f : adj;
                    float ee = e[k];
                    float xg = fmaf(gw0, ee, fmaf(gw1, adj, gbv));
                    float z  = sigmoid_fast(xg);
                    ee = fmaf(z, adj - ee, ee);
                    e[k] = ee;
                    rs += ee;
                    if (act) s_e[buf][m][c] = ee;
                }
                rs += __shfl_xor_sync(0xffffffffu, rs, 16);
                if (lane < Nn) {
                    float dis = rsqrtf(fmaxf(rs + 1.0f, 1e-6f));
                    s_q[buf][lane] = make_float4(de.x*dis, de.y*dis, de.z*dis, de.w*dis);
                    s_dis[buf][lane] = dis;
                }
                dcur = dnxt;
            }
        } else if (role == 1) {
            const int t = i - 1;
            if (t >= 0 && t < Tn) {
                const int buf = t & 1;
                float4 p = make_float4(0.f,0.f,0.f,0.f);
                float racc = 0.0f;
                #pragma unroll
                for (int k = 0; k < 7; k++) {
                    int m = m0 + k;
                    float em  = s_e[buf][m][c];
                    float4 qm = s_q[buf][m];
                    float dm  = s_dis[buf][m];
                    p.x = fmaf(em, qm.x, p.x);
                    p.y = fmaf(em, qm.y, p.y);
                    p.z = fmaf(em, qm.z, p.z);
                    p.w = fmaf(em, qm.w, p.w);
                    racc = fmaf(em, dm, racc);
                }
                p.x += __shfl_xor_sync(0xffffffffu, p.x, 16);
                p.y += __shfl_xor_sync(0xffffffffu, p.y, 16);
                p.z += __shfl_xor_sync(0xffffffffu, p.z, 16);
                p.w += __shfl_xor_sync(0xffffffffu, p.w, 16);
                racc += __shfl_xor_sync(0xffffffffu, racc, 16);
                if (lane < Nn) {
                    float dis = s_dis[buf][lane];
                    float4 q  = s_q[buf][lane];
                    float rr = dis * (racc + dis);
                    float x0 = (p.x + q.x) * dis;
                    float x1 = (p.y + q.y) * dis;
                    float x2 = (p.z + q.z) * dis;
                    float x3 = (p.w + q.w) * dis;
                    float mu = (x0*s_SWb[0] + x1*s_SWb[1] + x2*s_SWb[2]
                              + x3*s_SWb[3] + rr*s_SWb[4]) * (1.0f/32.0f);
                    float xt[5] = {x0, x1, x2, x3, rr};
                    float s2 = 0.0f;
                    #pragma unroll
                    for (int ii = 0; ii < 5; ii++) {
                        float rowd = 0.0f;
                        #pragma unroll
                        for (int jj = 0; jj < 5; jj++)
                            rowd = fmaf(s_G[ii*5+jj], xt[jj], rowd);
                        s2 = fmaf(xt[ii], rowd, s2);
                    }
                    s2 *= (1.0f/32.0f);
                    float var  = fmaf(-mu, mu, s2);
                    float istd = rsqrtf(var + 1e-5f);
                    s_xp[t & 3][lane] = make_float4(x0*istd, x1*istd, x2*istd, x3*istd);
                    s_mr[t & 3][lane] = make_float2(rr*istd, mu*istd);
                }
            }
        } else {
            const int wpar = role - 2;
            const int ts = i - 2;
            if (ts >= 0 && ts < Tn && (ts & 1) == wpar) {
                const int sb = ts & 3;
                float acc = 0.0f;
                #pragma unroll
                for (int n = 0; n < 7; n++) {
                    float4 xp = s_xp[sb][n];
                    float2 mr = s_mr[sb][n];
                    float hv = -mr.y;
                    hv = fmaf(xp.x, Wc0, hv);
                    hv = fmaf(xp.y, Wc1, hv);
                    hv = fmaf(xp.z, Wc2, hv);
                    hv = fmaf(xp.w, Wc3, hv);
                    hv = fmaf(mr.x, gcnb, hv);
                    acc += elu(fmaf(hv, lng, lnb));
                }
                geacc = acc;
            }
            const int tf = i - 3;
            if (tf >= 0 && tf < Tn && (tf & 1) == wpar) {
                const int sb = tf & 3;
                float acc = geacc;
                #pragma unroll
                for (int n = 7; n < Nn; n++) {
                    float4 xp = s_xp[sb][n];
                    float2 mr = s_mr[sb][n];
                    float hv = -mr.y;
                    hv = fmaf(xp.x, Wc0, hv);
                    hv = fmaf(xp.y, Wc1, hv);
                    hv = fmaf(xp.z, Wc2, hv);
                    hv = fmaf(xp.w, Wc3, hv);
                    hv = fmaf(mr.x, gcnb, hv);
                    acc += elu(fmaf(hv, lng, lnb));
                }
                float ge = acc * (1.0f / 14.0f);
                g_ge[((size_t)b * Tn + tf) * Hn + lane] = ge;
                float sc = warp_sum(ge * awv) + attnb;
                if (lane == 0) s_sc[tf] = sc;
            }
        }
        __syncthreads();
    }

    // ======================= inline fused tail =======================
    // P-warp publishes esm to shared for Jacobi
    if (role == 0 && c < Nn) {
        #pragma unroll
        for (int k = 0; k < 7; k++)
            s_A[(m0 + k) * Nn + c] = e[k];
    }
    __syncthreads();

    if (role == 0) {
        // ---- Jacobi (single warp, syncwarp only), 6 sweeps ----
        for (int sweep = 0; sweep < 6; sweep++) {
            for (int r = 0; r < 13; r++) {
                if (lane < 7) {
                    int pj = (lane == 0) ? 0 : 1 + (lane - 1 + r) % 13;
                    int qj = 1 + (12 - lane + r) % 13;
                    float apq = s_A[pj * Nn + qj];
                    float app = s_A[pj * Nn + pj];
                    float aqq = s_A[qj * Nn + qj];
                    float ap  = fabsf(apq);
                    float den = (ap > 1e-20f) ? apq : 1.0f;
                    float theta = __fdividef(0.5f * (aqq - app), den);
                    float tt = __fdividef(1.0f, fabsf(theta) + sqrtf(fmaf(theta, theta, 1.0f)));
                    tt = (theta < 0.0f) ? -tt : tt;
                    tt = (ap > 1e-20f) ? tt : 0.0f;
                    float cc = rsqrtf(fmaf(tt, tt, 1.0f));
                    s_cs[lane] = make_float2(cc, tt * cc);
                    s_pq[lane] = make_int2(pj, qj);
                }
                __syncwarp();
                #pragma unroll
                for (int idx = lane; idx < 98; idx += 32) {   // column pass
                    int row = idx / 7;
                    int kk  = idx - row * 7;
                    float2 cs = s_cs[kk];
                    int2   pq = s_pq[kk];
                    float ap_ = s_A[row * Nn + pq.x];
                    float aq_ = s_A[row * Nn + pq.y];
                    s_A[row * Nn + pq.x] = cs.x * ap_ - cs.y * aq_;
                    s_A[row * Nn + pq.y] = fmaf(cs.y, ap_, cs.x * aq_);
                }
                __syncwarp();
                #pragma unroll
                for (int idx = lane; idx < 98; idx += 32) {   // row pass
                    int col = idx / 7;
                    int kk  = idx - col * 7;
                    float2 cs = s_cs[kk];
                    int2   pq = s_pq[kk];
                    float pa = s_A[pq.x * Nn + col];
                    float qa = s_A[pq.y * Nn + col];
                    s_A[pq.x * Nn + col] = cs.x * pa - cs.y * qa;
                    s_A[pq.y * Nn + col] = fmaf(cs.y, pa, cs.x * qa);
                }
                __syncwarp();
            }
        }
        // top-5 eigenvalues ascending via parallel rank
        float ev = (lane < Nn) ? s_A[lane * Nn + lane] : 1e30f;
        int rank = 0;
        #pragma unroll
        for (int j = 0; j < Nn; j++) {
            float evj = s_A[j * Nn + j];
            rank += (evj < ev || (evj == ev && j < lane)) ? 1 : 0;
        }
        if (lane < Nn && rank >= Nn - 5) s_comb[rank - (Nn - 5)] = ev;
    } else {
        // ---- softmax pooling on the other 3 warps (named barrier 1, 96 thr) ----
        const int prole = role - 1;   // 0..2
        float m = -1e30f;
        #pragma unroll
        for (int k = lane; k < Tn; k += 32) m = fmaxf(m, s_sc[k]);
        m = warp_max(m);
        for (int k = prole * 32 + lane; k < Tn; k += 96)
            s_w[k] = __expf(s_sc[k] - m);
        asm volatile("bar.sync 1, 96;" ::: "memory");
        float s = 0.0f;
        #pragma unroll
        for (int k = lane; k < Tn; k += 32) s += s_w[k];
        s = warp_sum(s);
        // pooled: warp prole handles t = prole, prole+3, ... (coalesced ge reads)
        float acc = 0.0f;
        const float* gb = g_ge + (size_t)b * Tn * Hn + lane;
        for (int t = prole; t < Tn; t += 3)
            acc = fmaf(s_w[t], gb[t * Hn], acc);
        s_part[prole][lane] = acc;
        asm volatile("bar.sync 1, 96;" ::: "memory");
        if (prole == 0) {
            float pooled = s_part[0][lane] + s_part[1][lane] + s_part[2][lane];
            s_comb[5 + lane] = __fdividef(pooled, s);
        }
    }
    __syncthreads();

    // ---- classifier: 37 -> 64 (elu) -> 32 (elu) -> 2 ----
    if (tid < 64) {
        float a = c1_b[tid];
        #pragma unroll
        for (int i = 0; i < 37; i++)
            a = fmaf(s_comb[i], c1_w[i * 64 + tid], a);
        s_b1[tid] = elu(a);
    }
    __syncthreads();
    if (tid < 32) {
        float a2 = c2_b[lane];
        #pragma unroll
        for (int i = 0; i < 64; i++)
            a2 = fmaf(s_b1[i], c2_w[i * 32 + lane], a2);
        float h2 = elu(a2);
        float r0 = warp_sum(h2 * c3_w[lane * 2 + 0]);
        float r1 = warp_sum(h2 * c3_w[lane * 2 + 1]);
        if (lane == 0) {
            out[b * 2 + 0] = r0 + c3_b[0];
            out[b * 2 + 1] = r1 + c3_b[1];
        }
    }
}

extern "C" void kernel_launch(void* const* d_in, const int* in_sizes, int n_in,
                              void* d_out, int out_size)
{
    const float* ws     = (const float*)d_in[0];
    const float* gate_w = (const float*)d_in[1];
    const float* gate_b = (const float*)d_in[2];
    const float* gcn_w  = (const float*)d_in[3];
    const float* gcn_b  = (const float*)d_in[4];
    const float* ln_g   = (const float*)d_in[5];
    const float* ln_b   = (const float*)d_in[6];
    const float* attn_w = (const float*)d_in[7];
    const float* attn_b = (const float*)d_in[8];
    const float* c1_w   = (const float*)d_in[9];
    const float* c1_b   = (const float*)d_in[10];
    const float* c2_w   = (const float*)d_in[11];
    const float* c2_b   = (const float*)d_in[12];
    const float* c3_w   = (const float*)d_in[13];
    const float* c3_b   = (const float*)d_in[14];
    float* out = (float*)d_out;

    tgsm_fused<<<Bn, 128>>>(ws, gate_w, gate_b, gcn_w, gcn_b, ln_g, ln_b,
                            attn_w, attn_b, c1_w, c1_b, c2_w, c2_b,
                            c3_w, c3_b, out);
}

// round 10
// speedup vs baseline: 2.0770x; 1.2633x over previous
#include <cuda_runtime.h>
#include <cuda_bf16.h>

// TGSM v10: edge-parallel recurrence + fully t-parallel GCN tasks.
// Main kernel: CTA=batch; chunks of 32 t: [load+normalize] -> [91 edge threads
// advance gate recurrence 32 steps into smem] -> [4 warps x 8 independent
// (b,t) tasks: GCN+LN+ELU+ge+score]. Tail: warp=batch softmax pool + Jacobi
// + classifier, no block barriers.
// B=1024, T=256, N=14, Fd=4, H=32, K=5, C=2

#define Bn 1024
#define Tn 256
#define Nn 14
#define Hn 32

__device__ float g_ge[Bn * Tn * Hn];
__device__ float g_sc[Bn * Tn];
__device__ float g_esm_fin[Bn * 96];

__device__ __forceinline__ float warp_sum(float v) {
    v += __shfl_xor_sync(0xffffffffu, v, 16);
    v += __shfl_xor_sync(0xffffffffu, v, 8);
    v += __shfl_xor_sync(0xffffffffu, v, 4);
    v += __shfl_xor_sync(0xffffffffu, v, 2);
    v += __shfl_xor_sync(0xffffffffu, v, 1);
    return v;
}
__device__ __forceinline__ float warp_max(float v) {
    v = fmaxf(v, __shfl_xor_sync(0xffffffffu, v, 16));
    v = fmaxf(v, __shfl_xor_sync(0xffffffffu, v, 8));
    v = fmaxf(v, __shfl_xor_sync(0xffffffffu, v, 4));
    v = fmaxf(v, __shfl_xor_sync(0xffffffffu, v, 2));
    v = fmaxf(v, __shfl_xor_sync(0xffffffffu, v, 1));
    return v;
}
__device__ __forceinline__ float elu(float y) {
    return (y > 0.0f) ? y : (__expf(y) - 1.0f);
}
__device__ __forceinline__ float sigmoid_fast(float x) {
    float th;
    asm("tanh.approx.f32 %0, %1;" : "=f"(th) : "f"(0.5f * x));
    return fmaf(0.5f, th, 0.5f);
}
// map edge index e (0..90) to pair (n<m), row-major over upper triangle
__device__ __forceinline__ void edge_map(int e, int& n_, int& m_) {
    int n = 0, r = e, rl = 13;
    while (n < 13 && r >= rl) { r -= rl; rl--; n++; }
    n_ = n; m_ = n + 1 + r;
}

// ======================= Kernel 1: main =======================
__global__ __launch_bounds__(128, 7)
void tgsm_main(const float* __restrict__ ws,
               const float* __restrict__ gate_w, const float* __restrict__ gate_b,
               const float* __restrict__ gcn_w,  const float* __restrict__ gcn_b,
               const float* __restrict__ ln_g,   const float* __restrict__ ln_b,
               const float* __restrict__ attn_w, const float* __restrict__ attn_b)
{
    const int b    = blockIdx.x;
    const int tid  = threadIdx.x;
    const int lane = tid & 31;
    const int warp = tid >> 5;

    __shared__ float4 s_nrm[32][16];
    __shared__ float  s_len[32][16];
    __shared__ float  s_esm[32][92];
    __shared__ float  s_full[4][240];
    __shared__ float4 s_q[4][16];
    __shared__ float  s_dis[4][16];
    __shared__ float4 s_xp[4][16];
    __shared__ float2 s_mr[4][16];
    __shared__ float  s_G[25];
    __shared__ float  s_SWb[5];

    // constants needed by all threads (every warp does both phases)
    const float gw0 = gate_w[0], gw1 = gate_w[1], gbv = gate_b[0];
    const float Wc0 = gcn_w[0*Hn + lane];
    const float Wc1 = gcn_w[1*Hn + lane];
    const float Wc2 = gcn_w[2*Hn + lane];
    const float Wc3 = gcn_w[3*Hn + lane];
    const float gcnb = gcn_b[lane];
    const float lng = ln_g[lane], lnb = ln_b[lane];
    const float awv = attn_w[lane], attnb = attn_b[0];

    if (warp == 0) {
        float vW[5] = {Wc0, Wc1, Wc2, Wc3, gcnb};
        #pragma unroll
        for (int i2 = 0; i2 < 5; i2++) {
            #pragma unroll
            for (int j2 = i2; j2 < 5; j2++) {
                float g = warp_sum(vW[i2] * vW[j2]);
                if (lane == 0) { s_G[i2*5+j2] = g; s_G[j2*5+i2] = g; }
            }
            float sw = warp_sum(vW[i2]);
            if (lane == 0) s_SWb[i2] = sw;
        }
    }

    // task-phase edge maps (lane-based: edges lane, lane+32, lane+64)
    int n0, m0_, n1, m1_, n2 = 0, m2_ = 1;
    edge_map(lane, n0, m0_);
    edge_map(lane + 32, n1, m1_);
    if (lane < 27) edge_map(lane + 64, n2, m2_);

    // recurrence edge (tid-based)
    int rn = 0, rm = 1;
    const bool ract = (tid < 91);
    if (ract) edge_map(tid, rn, rm);
    float ee = 0.0f;

    const float4* src = reinterpret_cast<const float4*>(ws) + (size_t)b * (Tn * Nn);

    for (int ch = 0; ch < 8; ch++) {
        const int t0 = ch * 32;
        __syncthreads();     // also covers s_G/s_SWb on first iteration
        // ---- cooperative load + normalize: 32 steps x 14 nodes of de ----
        #pragma unroll
        for (int r2 = 0; r2 < 4; r2++) {
            int off = r2 * 128 + tid;
            if (off < 448) {
                float4 v = src[t0 * Nn + off];
                float d2 = v.x*v.x + v.y*v.y + v.z*v.z + v.w*v.w;
                float inv = rsqrtf(fmaxf(d2, 1e-24f));
                int tl2 = off / 14;
                int nd  = off - tl2 * 14;
                s_nrm[tl2][nd] = make_float4(v.x*inv, v.y*inv, v.z*inv, v.w*inv);
                s_len[tl2][nd] = d2 * inv;   // = |de|
            }
        }
        __syncthreads();
        // ---- edge recurrence: 32 steps ----
        if (ract) {
            #pragma unroll 8
            for (int k = 0; k < 32; k++) {
                float4 a  = s_nrm[k][rn];
                float4 c4 = s_nrm[k][rm];
                float dot = a.x * c4.x;
                dot = fmaf(a.y, c4.y, dot);
                dot = fmaf(a.z, c4.z, dot);
                dot = fmaf(a.w, c4.w, dot);
                float adj = fmaf(dot, 0.5f, 0.5f);
                float xg = fmaf(gw0, ee, fmaf(gw1, adj, gbv));
                float z  = sigmoid_fast(xg);
                ee = fmaf(z, adj - ee, ee);
                s_esm[k][tid] = ee;
            }
        }
        __syncthreads();
        // ---- tasks: warp w handles t_local = w, w+4, ..., w+28 ----
        #pragma unroll 1
        for (int j = 0; j < 8; j++) {
            const int tl = warp + 4 * j;
            float* sf = s_full[warp];
            // gather esm values and scatter to full matrix (stride 17)
            float v0 = s_esm[tl][lane];
            float v1 = s_esm[tl][lane + 32];
            float v2 = (lane < 27) ? s_esm[tl][lane + 64] : 0.0f;
            sf[n0*17 + m0_] = v0;  sf[m0_*17 + n0] = v0;
            sf[n1*17 + m1_] = v1;  sf[m1_*17 + n1] = v1;
            if (lane < 27) { sf[n2*17 + m2_] = v2;  sf[m2_*17 + n2] = v2; }
            if (lane < 14) sf[lane * 18] = 0.0f;
            __syncwarp();
            float4 qreg = make_float4(0.f,0.f,0.f,0.f);
            float dis = 0.0f;
            if (lane < 14) {
                float rs = 1.0f;
                #pragma unroll
                for (int m3 = 0; m3 < 14; m3++) rs += sf[lane*17 + m3];
                dis = rsqrtf(fmaxf(rs, 1e-6f));
                float4 nr = s_nrm[tl][lane];
                float f = s_len[tl][lane] * dis;
                qreg = make_float4(nr.x*f, nr.y*f, nr.z*f, nr.w*f);
                s_q[warp][lane] = qreg;
                s_dis[warp][lane] = dis;
            }
            __syncwarp();
            if (lane < 14) {
                float4 p = make_float4(0.f,0.f,0.f,0.f);
                float racc = 0.0f;
                #pragma unroll
                for (int m3 = 0; m3 < 14; m3++) {
                    float ev  = sf[lane*17 + m3];
                    float4 qm = s_q[warp][m3];
                    float dm  = s_dis[warp][m3];
                    p.x = fmaf(ev, qm.x, p.x);
                    p.y = fmaf(ev, qm.y, p.y);
                    p.z = fmaf(ev, qm.z, p.z);
                    p.w = fmaf(ev, qm.w, p.w);
                    racc = fmaf(ev, dm, racc);
                }
                float rr = dis * (racc + dis);
                float x0 = (p.x + qreg.x) * dis;
                float x1 = (p.y + qreg.y) * dis;
                float x2 = (p.z + qreg.z) * dis;
                float x3 = (p.w + qreg.w) * dis;
                float mu = (x0*s_SWb[0] + x1*s_SWb[1] + x2*s_SWb[2]
                          + x3*s_SWb[3] + rr*s_SWb[4]) * (1.0f/32.0f);
                float xt[5] = {x0, x1, x2, x3, rr};
                float s2 = 0.0f;
                #pragma unroll
                for (int ii = 0; ii < 5; ii++) {
                    float rowd = 0.0f;
                    #pragma unroll
                    for (int jj = 0; jj < 5; jj++)
                        rowd = fmaf(s_G[ii*5+jj], xt[jj], rowd);
                    s2 = fmaf(xt[ii], rowd, s2);
                }
                s2 *= (1.0f/32.0f);
                float var  = fmaf(-mu, mu, s2);
                float istd = rsqrtf(var + 1e-5f);
                s_xp[warp][lane] = make_float4(x0*istd, x1*istd, x2*istd, x3*istd);
                s_mr[warp][lane] = make_float2(rr*istd, mu*istd);
            }
            __syncwarp();
            float acc = 0.0f;
            #pragma unroll
            for (int nq = 0; nq < 14; nq++) {
                float4 xp = s_xp[warp][nq];
                float2 mr = s_mr[warp][nq];
                float hv = -mr.y;
                hv = fmaf(xp.x, Wc0, hv);
                hv = fmaf(xp.y, Wc1, hv);
                hv = fmaf(xp.z, Wc2, hv);
                hv = fmaf(xp.w, Wc3, hv);
                hv = fmaf(mr.x, gcnb, hv);
                acc += elu(fmaf(hv, lng, lnb));
            }
            float ge = acc * (1.0f / 14.0f);
            const int gt = t0 + tl;
            g_ge[((size_t)b * Tn + gt) * Hn + lane] = ge;
            float scv = warp_sum(ge * awv) + attnb;
            if (lane == 0) g_sc[b * Tn + gt] = scv;
            __syncwarp();
        }
    }
    if (ract) g_esm_fin[b * 96 + tid] = ee;
}

// ======================= Kernel 2: tail (warp = batch) =======================
__global__ __launch_bounds__(256)
void tgsm_tail(const float* __restrict__ c1_w, const float* __restrict__ c1_b,
               const float* __restrict__ c2_w, const float* __restrict__ c2_b,
               const float* __restrict__ c3_w, const float* __restrict__ c3_b,
               float* __restrict__ out)
{
    const int tid  = threadIdx.x;
    const int lane = tid & 31;
    const int w    = tid >> 5;
    const int b    = blockIdx.x * 8 + w;

    __shared__ float  s_c1w[37 * 64];
    __shared__ float  s_c1b[64];
    __shared__ float  s_c2w[64 * 32];
    __shared__ float  s_c2b[32];
    __shared__ float  s_c3w[64];
    __shared__ float  s_c3b[2];
    __shared__ float  s_full[8][240];
    __shared__ float2 s_cs[8][7];
    __shared__ int2   s_pq[8][7];
    __shared__ float  s_comb[8][40];
    __shared__ float  s_b1[8][64];

    for (int i = tid; i < 37 * 64; i += 256) s_c1w[i] = c1_w[i];
    for (int i = tid; i < 64 * 32; i += 256) s_c2w[i] = c2_w[i];
    if (tid < 64) s_c1b[tid] = c1_b[tid];
    if (tid < 32) s_c2b[tid] = c2_b[tid];
    if (tid < 64) s_c3w[tid] = c3_w[tid];
    if (tid < 2)  s_c3b[tid] = c3_b[tid];
    __syncthreads();

    // ---- exact softmax pooling (warp-local) ----
    float sw[8];
    #pragma unroll
    for (int k = 0; k < 8; k++) sw[k] = g_sc[b * Tn + k * 32 + lane];
    float m = sw[0];
    #pragma unroll
    for (int k = 1; k < 8; k++) m = fmaxf(m, sw[k]);
    m = warp_max(m);
    float ssum = 0.0f;
    #pragma unroll
    for (int k = 0; k < 8; k++) { sw[k] = __expf(sw[k] - m); ssum += sw[k]; }
    ssum = warp_sum(ssum);

    float acc = 0.0f;
    const float* gb = g_ge + (size_t)b * Tn * Hn + lane;
    #pragma unroll 1
    for (int k = 0; k < 8; k++) {
        #pragma unroll 8
        for (int s = 0; s < 32; s++) {
            float wt = __shfl_sync(0xffffffffu, sw[k], s);
            acc = fmaf(wt, gb[(k * 32 + s) * Hn], acc);
        }
    }
    s_comb[w][5 + lane] = __fdividef(acc, ssum);

    // ---- build final esm matrix ----
    int n0, m0_, n1, m1_, n2 = 0, m2_ = 1;
    edge_map(lane, n0, m0_);
    edge_map(lane + 32, n1, m1_);
    if (lane < 27) edge_map(lane + 64, n2, m2_);
    float* sf = s_full[w];
    float v0 = g_esm_fin[b * 96 + lane];
    float v1 = g_esm_fin[b * 96 + lane + 32];
    float v2 = (lane < 27) ? g_esm_fin[b * 96 + lane + 64] : 0.0f;
    sf[n0*17 + m0_] = v0;  sf[m0_*17 + n0] = v0;
    sf[n1*17 + m1_] = v1;  sf[m1_*17 + n1] = v1;
    if (lane < 27) { sf[n2*17 + m2_] = v2;  sf[m2_*17 + n2] = v2; }
    if (lane < 14) sf[lane * 18] = 0.0f;
    __syncwarp();

    // precomputed update-pass indices
    int rowi[4], kki[4];
    #pragma unroll
    for (int ii = 0; ii < 4; ii++) {
        int idx = lane + 32 * ii;
        rowi[ii] = idx / 7;
        kki[ii]  = idx - rowi[ii] * 7;
    }

    // ---- warp-local parallel Jacobi: 6 sweeps x 13 rounds ----
    for (int sweep = 0; sweep < 6; sweep++) {
        for (int r = 0; r < 13; r++) {
            if (lane < 7) {
                int pj = (lane == 0) ? 0 : 1 + (lane - 1 + r) % 13;
                int qj = 1 + (12 - lane + r) % 13;
                float apq = sf[pj*17 + qj];
                float app = sf[pj*18];
                float aqq = sf[qj*18];
                float ap  = fabsf(apq);
                float den = (ap > 1e-20f) ? apq : 1.0f;
                float theta = __fdividef(0.5f * (aqq - app), den);
                float tt = __fdividef(1.0f, fabsf(theta) + sqrtf(fmaf(theta, theta, 1.0f)));
                tt = (theta < 0.0f) ? -tt : tt;
                tt = (ap > 1e-20f) ? tt : 0.0f;
                float cc = rsqrtf(fmaf(tt, tt, 1.0f));
                s_cs[w][lane] = make_float2(cc, tt * cc);
                s_pq[w][lane] = make_int2(pj, qj);
            }
            __syncwarp();
            #pragma unroll
            for (int ii = 0; ii < 4; ii++) {
                int idx = lane + 32 * ii;
                if (idx < 98) {
                    float2 cs = s_cs[w][kki[ii]];
                    int2   pq = s_pq[w][kki[ii]];
                    int row = rowi[ii];
                    float a1 = sf[row*17 + pq.x];
                    float a2 = sf[row*17 + pq.y];
                    sf[row*17 + pq.x] = cs.x * a1 - cs.y * a2;
                    sf[row*17 + pq.y] = fmaf(cs.y, a1, cs.x * a2);
                }
            }
            __syncwarp();
            #pragma unroll
            for (int ii = 0; ii < 4; ii++) {
                int idx = lane + 32 * ii;
                if (idx < 98) {
                    float2 cs = s_cs[w][kki[ii]];
                    int2   pq = s_pq[w][kki[ii]];
                    int col = rowi[ii];
                    float a1 = sf[pq.x*17 + col];
                    float a2 = sf[pq.y*17 + col];
                    sf[pq.x*17 + col] = cs.x * a1 - cs.y * a2;
                    sf[pq.y*17 + col] = fmaf(cs.y, a1, cs.x * a2);
                }
            }
            __syncwarp();
        }
    }
    // top-5 eigenvalues ascending via parallel rank
    {
        float ev = (lane < 14) ? sf[lane * 18] : 1e30f;
        int rank = 0;
        #pragma unroll
        for (int j2 = 0; j2 < 14; j2++) {
            float evj = sf[j2 * 18];
            rank += (evj < ev || (evj == ev && j2 < lane)) ? 1 : 0;
        }
        if (lane < 14 && rank >= 9) s_comb[w][rank - 9] = ev;
    }
    __syncwarp();

    // ---- classifier: 37 -> 64 (elu) -> 32 (elu) -> 2 (warp-local) ----
    float a0 = s_c1b[lane], a1 = s_c1b[lane + 32];
    #pragma unroll
    for (int i = 0; i < 37; i++) {
        float ci = s_comb[w][i];
        a0 = fmaf(ci, s_c1w[i*64 + lane], a0);
        a1 = fmaf(ci, s_c1w[i*64 + 32 + lane], a1);
    }
    s_b1[w][lane]      = elu(a0);
    s_b1[w][lane + 32] = elu(a1);
    __syncwarp();
    float a2 = s_c2b[lane];
    #pragma unroll
    for (int i = 0; i < 64; i++)
        a2 = fmaf(s_b1[w][i], s_c2w[i*32 + lane], a2);
    float h2 = elu(a2);
    float r0 = warp_sum(h2 * s_c3w[lane*2 + 0]);
    float r1 = warp_sum(h2 * s_c3w[lane*2 + 1]);
    if (lane == 0) {
        out[b*2 + 0] = r0 + s_c3b[0];
        out[b*2 + 1] = r1 + s_c3b[1];
    }
}

extern "C" void kernel_launch(void* const* d_in, const int* in_sizes, int n_in,
                              void* d_out, int out_size)
{
    const float* ws     = (const float*)d_in[0];
    const float* gate_w = (const float*)d_in[1];
    const float* gate_b = (const float*)d_in[2];
    const float* gcn_w  = (const float*)d_in[3];
    const float* gcn_b  = (const float*)d_in[4];
    const float* ln_g   = (const float*)d_in[5];
    const float* ln_b   = (const float*)d_in[6];
    const float* attn_w = (const float*)d_in[7];
    const float* attn_b = (const float*)d_in[8];
    const float* c1_w   = (const float*)d_in[9];
    const float* c1_b   = (const float*)d_in[10];
    const float* c2_w   = (const float*)d_in[11];
    const float* c2_b   = (const float*)d_in[12];
    const float* c3_w   = (const float*)d_in[13];
    const float* c3_b   = (const float*)d_in[14];
    float* out = (float*)d_out;

    tgsm_main<<<Bn, 128>>>(ws, gate_w, gate_b, gcn_w, gcn_b, ln_g, ln_b,
                           attn_w, attn_b);
    tgsm_tail<<<Bn / 8, 256>>>(c1_w, c1_b, c2_w, c2_b, c3_w, c3_b, out);
}

// round 11
// speedup vs baseline: 2.2589x; 1.0876x over previous
#include <cuda_runtime.h>
#include <cuda_bf16.h>

// TGSM v11: single fused kernel. Edge-parallel gate recurrence + t-parallel
// GCN tasks + per-warp ONLINE softmax pooling (no g_ge), inline Jacobi +
// classifier. Zero device-global scratch.
// B=1024, T=256, N=14, Fd=4, H=32, K=5, C=2

#define Bn 1024
#define Tn 256
#define Nn 14
#define Hn 32

__device__ __forceinline__ float warp_sum(float v) {
    v += __shfl_xor_sync(0xffffffffu, v, 16);
    v += __shfl_xor_sync(0xffffffffu, v, 8);
    v += __shfl_xor_sync(0xffffffffu, v, 4);
    v += __shfl_xor_sync(0xffffffffu, v, 2);
    v += __shfl_xor_sync(0xffffffffu, v, 1);
    return v;
}
__device__ __forceinline__ float elu(float y) {
    return (y > 0.0f) ? y : (__expf(y) - 1.0f);
}
__device__ __forceinline__ float sigmoid_fast(float x) {
    float th;
    asm("tanh.approx.f32 %0, %1;" : "=f"(th) : "f"(0.5f * x));
    return fmaf(0.5f, th, 0.5f);
}
// map edge index e (0..90) to pair (n<m), row-major over upper triangle
__device__ __forceinline__ void edge_map(int e, int& n_, int& m_) {
    int n = 0, r = e, rl = 13;
    while (n < 13 && r >= rl) { r -= rl; rl--; n++; }
    n_ = n; m_ = n + 1 + r;
}

__global__ __launch_bounds__(128, 7)
void tgsm_fused(const float* __restrict__ ws,
                const float* __restrict__ gate_w, const float* __restrict__ gate_b,
                const float* __restrict__ gcn_w,  const float* __restrict__ gcn_b,
                const float* __restrict__ ln_g,   const float* __restrict__ ln_b,
                const float* __restrict__ attn_w, const float* __restrict__ attn_b,
                const float* __restrict__ c1_w,   const float* __restrict__ c1_b,
                const float* __restrict__ c2_w,   const float* __restrict__ c2_b,
                const float* __restrict__ c3_w,   const float* __restrict__ c3_b,
                float* __restrict__ out)
{
    const int b    = blockIdx.x;
    const int tid  = threadIdx.x;
    const int lane = tid & 31;
    const int warp = tid >> 5;

    __shared__ float4 s_nrm[32][16];
    __shared__ float  s_len[32][16];
    __shared__ float  s_esm[32][92];
    __shared__ float  s_full[4][240];
    __shared__ float4 s_q[4][16];
    __shared__ float  s_dis[4][16];
    __shared__ float4 s_xp[4][16];
    __shared__ float2 s_mr[4][16];
    __shared__ float  s_G[25];
    __shared__ float  s_SWb[5];
    __shared__ float  s_pool[4][Hn];
    __shared__ float2 s_MS[4];
    __shared__ float2 s_cs[7];
    __shared__ int2   s_pq[7];
    __shared__ float  s_comb[5 + Hn];
    __shared__ float  s_b1[64];

    // constants (all warps run both phases)
    const float gw0 = gate_w[0], gw1 = gate_w[1], gbv = gate_b[0];
    const float Wc0 = gcn_w[0*Hn + lane];
    const float Wc1 = gcn_w[1*Hn + lane];
    const float Wc2 = gcn_w[2*Hn + lane];
    const float Wc3 = gcn_w[3*Hn + lane];
    const float gcnb = gcn_b[lane];
    const float lng = ln_g[lane], lnb = ln_b[lane];
    const float awv = attn_w[lane], attnb = attn_b[0];

    if (warp == 0) {
        float vW[5] = {Wc0, Wc1, Wc2, Wc3, gcnb};
        #pragma unroll
        for (int i2 = 0; i2 < 5; i2++) {
            #pragma unroll
            for (int j2 = i2; j2 < 5; j2++) {
                float g = warp_sum(vW[i2] * vW[j2]);
                if (lane == 0) { s_G[i2*5+j2] = g; s_G[j2*5+i2] = g; }
            }
            float sw = warp_sum(vW[i2]);
            if (lane == 0) s_SWb[i2] = sw;
        }
    }

    // task-phase edge maps (lane-based: edges lane, lane+32, lane+64)
    int n0, m0_, n1, m1_, n2 = 0, m2_ = 1;
    edge_map(lane, n0, m0_);
    edge_map(lane + 32, n1, m1_);
    if (lane < 27) edge_map(lane + 64, n2, m2_);

    // recurrence edge (tid-based)
    int rn = 0, rm = 1;
    const bool ract = (tid < 91);
    if (ract) edge_map(tid, rn, rm);
    float ee = 0.0f;

    // per-warp online softmax state (lane = channel)
    float Pol = 0.0f, Mol = -1e30f, Sol = 0.0f;

    const float4* src = reinterpret_cast<const float4*>(ws) + (size_t)b * (Tn * Nn);

    for (int ch = 0; ch < 8; ch++) {
        const int t0 = ch * 32;
        __syncthreads();     // also covers s_G/s_SWb on first iteration
        // ---- cooperative load + normalize: 32 steps x 14 nodes ----
        #pragma unroll
        for (int r2 = 0; r2 < 4; r2++) {
            int off = r2 * 128 + tid;
            if (off < 448) {
                float4 v = src[t0 * Nn + off];
                float d2 = v.x*v.x + v.y*v.y + v.z*v.z + v.w*v.w;
                float inv = rsqrtf(fmaxf(d2, 1e-24f));
                int tl2 = off / 14;
                int nd  = off - tl2 * 14;
                s_nrm[tl2][nd] = make_float4(v.x*inv, v.y*inv, v.z*inv, v.w*inv);
                s_len[tl2][nd] = d2 * inv;   // = |de|
            }
        }
        __syncthreads();
        // ---- edge recurrence: 32 steps ----
        if (ract) {
            #pragma unroll 8
            for (int k = 0; k < 32; k++) {
                float4 a  = s_nrm[k][rn];
                float4 c4 = s_nrm[k][rm];
                float dot = a.x * c4.x;
                dot = fmaf(a.y, c4.y, dot);
                dot = fmaf(a.z, c4.z, dot);
                dot = fmaf(a.w, c4.w, dot);
                float adj = fmaf(dot, 0.5f, 0.5f);
                float xg = fmaf(gw0, ee, fmaf(gw1, adj, gbv));
                float z  = sigmoid_fast(xg);
                ee = fmaf(z, adj - ee, ee);
                s_esm[k][tid] = ee;
            }
        }
        __syncthreads();
        // ---- tasks: warp w handles t_local = w, w+4, ..., w+28 ----
        #pragma unroll 1
        for (int j = 0; j < 8; j++) {
            const int tl = warp + 4 * j;
            float* sf = s_full[warp];
            float v0 = s_esm[tl][lane];
            float v1 = s_esm[tl][lane + 32];
            float v2 = (lane < 27) ? s_esm[tl][lane + 64] : 0.0f;
            sf[n0*17 + m0_] = v0;  sf[m0_*17 + n0] = v0;
            sf[n1*17 + m1_] = v1;  sf[m1_*17 + n1] = v1;
            if (lane < 27) { sf[n2*17 + m2_] = v2;  sf[m2_*17 + n2] = v2; }
            if (lane < 14) sf[lane * 18] = 0.0f;
            __syncwarp();
            float4 qreg = make_float4(0.f,0.f,0.f,0.f);
            float dis = 0.0f;
            if (lane < 14) {
                float rs = 1.0f;
                #pragma unroll
                for (int m3 = 0; m3 < 14; m3++) rs += sf[lane*17 + m3];
                dis = rsqrtf(fmaxf(rs, 1e-6f));
                float4 nr = s_nrm[tl][lane];
                float f = s_len[tl][lane] * dis;
                qreg = make_float4(nr.x*f, nr.y*f, nr.z*f, nr.w*f);
                s_q[warp][lane] = qreg;
                s_dis[warp][lane] = dis;
            }
            __syncwarp();
            if (lane < 14) {
                float4 p = make_float4(0.f,0.f,0.f,0.f);
                float racc = 0.0f;
                #pragma unroll
                for (int m3 = 0; m3 < 14; m3++) {
                    float ev  = sf[lane*17 + m3];
                    float4 qm = s_q[warp][m3];
                    float dm  = s_dis[warp][m3];
                    p.x = fmaf(ev, qm.x, p.x);
                    p.y = fmaf(ev, qm.y, p.y);
                    p.z = fmaf(ev, qm.z, p.z);
                    p.w = fmaf(ev, qm.w, p.w);
                    racc = fmaf(ev, dm, racc);
                }
                float rr = dis * (racc + dis);
                float x0 = (p.x + qreg.x) * dis;
                float x1 = (p.y + qreg.y) * dis;
                float x2 = (p.z + qreg.z) * dis;
                float x3 = (p.w + qreg.w) * dis;
                float mu = (x0*s_SWb[0] + x1*s_SWb[1] + x2*s_SWb[2]
                          + x3*s_SWb[3] + rr*s_SWb[4]) * (1.0f/32.0f);
                float xt[5] = {x0, x1, x2, x3, rr};
                float s2 = 0.0f;
                #pragma unroll
                for (int ii = 0; ii < 5; ii++) {
                    float rowd = 0.0f;
                    #pragma unroll
                    for (int jj = 0; jj < 5; jj++)
                        rowd = fmaf(s_G[ii*5+jj], xt[jj], rowd);
                    s2 = fmaf(xt[ii], rowd, s2);
                }
                s2 *= (1.0f/32.0f);
                float var  = fmaf(-mu, mu, s2);
                float istd = rsqrtf(var + 1e-5f);
                s_xp[warp][lane] = make_float4(x0*istd, x1*istd, x2*istd, x3*istd);
                s_mr[warp][lane] = make_float2(rr*istd, mu*istd);
            }
            __syncwarp();
            float acc = 0.0f;
            #pragma unroll
            for (int nq = 0; nq < 14; nq++) {
                float4 xp = s_xp[warp][nq];
                float2 mr = s_mr[warp][nq];
                float hv = -mr.y;
                hv = fmaf(xp.x, Wc0, hv);
                hv = fmaf(xp.y, Wc1, hv);
                hv = fmaf(xp.z, Wc2, hv);
                hv = fmaf(xp.w, Wc3, hv);
                hv = fmaf(mr.x, gcnb, hv);
                acc += elu(fmaf(hv, lng, lnb));
            }
            float ge = acc * (1.0f / 14.0f);
            // ---- online softmax pooling update (per-warp, exact) ----
            float scv = warp_sum(ge * awv) + attnb;
            float nM = fmaxf(Mol, scv);
            float al = __expf(Mol - nM);
            float wt = __expf(scv - nM);
            Pol = fmaf(Pol, al, wt * ge);
            Sol = fmaf(Sol, al, wt);
            Mol = nM;
            __syncwarp();
        }
    }

    // ---- publish per-warp pool state + final esm ----
    s_pool[warp][lane] = Pol;
    if (lane == 0) s_MS[warp] = make_float2(Mol, Sol);
    __syncthreads();
    {
        float* sf0 = s_full[0];
        if (ract) {
            sf0[rn*17 + rm] = ee;
            sf0[rm*17 + rn] = ee;
        }
        if (tid < 14) sf0[tid * 18] = 0.0f;
    }
    __syncthreads();

    if (warp == 0) {
        // ---- combine 4 online-softmax partials (exact) ----
        float2 ms0 = s_MS[0], ms1 = s_MS[1], ms2 = s_MS[2], ms3 = s_MS[3];
        float M = fmaxf(fmaxf(ms0.x, ms1.x), fmaxf(ms2.x, ms3.x));
        float f0 = __expf(ms0.x - M), f1 = __expf(ms1.x - M);
        float f2 = __expf(ms2.x - M), f3 = __expf(ms3.x - M);
        float P = s_pool[0][lane]*f0 + s_pool[1][lane]*f1
                + s_pool[2][lane]*f2 + s_pool[3][lane]*f3;
        float S = ms0.y*f0 + ms1.y*f1 + ms2.y*f2 + ms3.y*f3;
        s_comb[5 + lane] = __fdividef(P, S);
    } else if (warp == 3) {
        // ---- warp-local parallel Jacobi on s_full[0]: 6 sweeps ----
        float* sf = s_full[0];
        int rowi[4], kki[4];
        #pragma unroll
        for (int ii = 0; ii < 4; ii++) {
            int idx = lane + 32 * ii;
            rowi[ii] = idx / 7;
            kki[ii]  = idx - rowi[ii] * 7;
        }
        for (int sweep = 0; sweep < 6; sweep++) {
            for (int r = 0; r < 13; r++) {
                if (lane < 7) {
                    int pj = (lane == 0) ? 0 : 1 + (lane - 1 + r) % 13;
                    int qj = 1 + (12 - lane + r) % 13;
                    float apq = sf[pj*17 + qj];
                    float app = sf[pj*18];
                    float aqq = sf[qj*18];
                    float ap  = fabsf(apq);
                    float den = (ap > 1e-20f) ? apq : 1.0f;
                    float theta = __fdividef(0.5f * (aqq - app), den);
                    float tt = __fdividef(1.0f, fabsf(theta) + sqrtf(fmaf(theta, theta, 1.0f)));
                    tt = (theta < 0.0f) ? -tt : tt;
                    tt = (ap > 1e-20f) ? tt : 0.0f;
                    float cc = rsqrtf(fmaf(tt, tt, 1.0f));
                    s_cs[lane] = make_float2(cc, tt * cc);
                    s_pq[lane] = make_int2(pj, qj);
                }
                __syncwarp();
                #pragma unroll
                for (int ii = 0; ii < 4; ii++) {
                    int idx = lane + 32 * ii;
                    if (idx < 98) {
                        float2 cs = s_cs[kki[ii]];
                        int2   pq = s_pq[kki[ii]];
                        int row = rowi[ii];
                        float a1 = sf[row*17 + pq.x];
                        float a2 = sf[row*17 + pq.y];
                        sf[row*17 + pq.x] = cs.x * a1 - cs.y * a2;
                        sf[row*17 + pq.y] = fmaf(cs.y, a1, cs.x * a2);
                    }
                }
                __syncwarp();
                #pragma unroll
                for (int ii = 0; ii < 4; ii++) {
                    int idx = lane + 32 * ii;
                    if (idx < 98) {
                        float2 cs = s_cs[kki[ii]];
                        int2   pq = s_pq[kki[ii]];
                        int col = rowi[ii];
                        float a1 = sf[pq.x*17 + col];
                        float a2 = sf[pq.y*17 + col];
                        sf[pq.x*17 + col] = cs.x * a1 - cs.y * a2;
                        sf[pq.y*17 + col] = fmaf(cs.y, a1, cs.x * a2);
                    }
                }
                __syncwarp();
            }
        }
        // top-5 eigenvalues ascending via parallel rank
        float ev = (lane < 14) ? sf[lane * 18] : 1e30f;
        int rank = 0;
        #pragma unroll
        for (int j2 = 0; j2 < 14; j2++) {
            float evj = sf[j2 * 18];
            rank += (evj < ev || (evj == ev && j2 < lane)) ? 1 : 0;
        }
        if (lane < 14 && rank >= 9) s_comb[rank - 9] = ev;
    }
    __syncthreads();

    // ---- classifier: 37 -> 64 (elu) -> 32 (elu) -> 2 ----
    if (tid < 64) {
        float a = c1_b[tid];
        #pragma unroll
        for (int i = 0; i < 37; i++)
            a = fmaf(s_comb[i], c1_w[i * 64 + tid], a);
        s_b1[tid] = elu(a);
    }
    __syncthreads();
    if (tid < 32) {
        float a2 = c2_b[lane];
        #pragma unroll
        for (int i = 0; i < 64; i++)
            a2 = fmaf(s_b1[i], c2_w[i * 32 + lane], a2);
        float h2 = elu(a2);
        float r0 = warp_sum(h2 * c3_w[lane * 2 + 0]);
        float r1 = warp_sum(h2 * c3_w[lane * 2 + 1]);
        if (lane == 0) {
            out[b * 2 + 0] = r0 + c3_b[0];
            out[b * 2 + 1] = r1 + c3_b[1];
        }
    }
}

extern "C" void kernel_launch(void* const* d_in, const int* in_sizes, int n_in,
                              void* d_out, int out_size)
{
    const float* ws     = (const float*)d_in[0];
    const float* gate_w = (const float*)d_in[1];
    const float* gate_b = (const float*)d_in[2];
    const float* gcn_w  = (const float*)d_in[3];
    const float* gcn_b  = (const float*)d_in[4];
    const float* ln_g   = (const float*)d_in[5];
    const float* ln_b   = (const float*)d_in[6];
    const float* attn_w = (const float*)d_in[7];
    const float* attn_b = (const float*)d_in[8];
    const float* c1_w   = (const float*)d_in[9];
    const float* c1_b   = (const float*)d_in[10];
    const float* c2_w   = (const float*)d_in[11];
    const float* c2_b   = (const float*)d_in[12];
    const float* c3_w   = (const float*)d_in[13];
    const float* c3_b   = (const float*)d_in[14];
    float* out = (float*)d_out;

    tgsm_fused<<<Bn, 128>>>(ws, gate_w, gate_b, gcn_w, gcn_b, ln_g, ln_b,
                            attn_w, attn_b, c1_w, c1_b, c2_w, c2_b,
                            c3_w, c3_b, out);
}

// round 12
// speedup vs baseline: 2.6863x; 1.1892x over previous
#include <cuda_runtime.h>
#include <cuda_bf16.h>

// TGSM v12: fused kernel; recurrence writes full symmetric esm matrices
// (vectorized row reads), dual-task half-warps for node phases, online
// softmax pooling, inline Jacobi + classifier. Zero global scratch.
// B=1024, T=256, N=14, Fd=4, H=32, K=5, C=2

#define Bn 1024
#define Tn 256
#define Nn 14
#define Hn 32
#define CH 16          // chunk length (t steps per chunk)
#define RS 20          // row stride (floats) in the esm matrix

__device__ __forceinline__ float warp_sum(float v) {
    v += __shfl_xor_sync(0xffffffffu, v, 16);
    v += __shfl_xor_sync(0xffffffffu, v, 8);
    v += __shfl_xor_sync(0xffffffffu, v, 4);
    v += __shfl_xor_sync(0xffffffffu, v, 2);
    v += __shfl_xor_sync(0xffffffffu, v, 1);
    return v;
}
__device__ __forceinline__ float elu(float y) {
    return (y > 0.0f) ? y : (__expf(y) - 1.0f);
}
__device__ __forceinline__ float sigmoid_fast(float x) {
    float th;
    asm("tanh.approx.f32 %0, %1;" : "=f"(th) : "f"(0.5f * x));
    return fmaf(0.5f, th, 0.5f);
}
// map edge index e (0..90) to pair (n<m), row-major over upper triangle
__device__ __forceinline__ void edge_map(int e, int& n_, int& m_) {
    int n = 0, r = e, rl = 13;
    while (n < 13 && r >= rl) { r -= rl; rl--; n++; }
    n_ = n; m_ = n + 1 + r;
}

__global__ __launch_bounds__(128, 7)
void tgsm_fused(const float* __restrict__ ws,
                const float* __restrict__ gate_w, const float* __restrict__ gate_b,
                const float* __restrict__ gcn_w,  const float* __restrict__ gcn_b,
                const float* __restrict__ ln_g,   const float* __restrict__ ln_b,
                const float* __restrict__ attn_w, const float* __restrict__ attn_b,
                const float* __restrict__ c1_w,   const float* __restrict__ c1_b,
                const float* __restrict__ c2_w,   const float* __restrict__ c2_b,
                const float* __restrict__ c3_w,   const float* __restrict__ c3_b,
                float* __restrict__ out)
{
    const int b    = blockIdx.x;
    const int tid  = threadIdx.x;
    const int lane = tid & 31;
    const int warp = tid >> 5;
    const int half = lane >> 4;    // dual-task half
    const int c    = lane & 15;    // node index within half

    __shared__ __align__(16) float4 s_nrm[CH][16];
    __shared__ float  s_len[CH][16];
    __shared__ __align__(16) float s_esmF[CH][Nn * RS];  // full sym matrices
    __shared__ float4 s_q[4][2][16];
    __shared__ float  s_dis[4][2][16];
    __shared__ float4 s_xp[4][2][16];
    __shared__ float2 s_mr[4][2][16];
    __shared__ float  s_G[25];
    __shared__ float  s_SWb[5];
    __shared__ float  s_pool[4][Hn];
    __shared__ float2 s_MS[4];
    __shared__ float2 s_cs[7];
    __shared__ int2   s_pq[7];
    __shared__ float  s_comb[5 + Hn];
    __shared__ float  s_b1[64];

    // constants (all warps run all phases)
    const float gw0 = gate_w[0], gw1 = gate_w[1], gbv = gate_b[0];
    const float Wc0 = gcn_w[0*Hn + lane];
    const float Wc1 = gcn_w[1*Hn + lane];
    const float Wc2 = gcn_w[2*Hn + lane];
    const float Wc3 = gcn_w[3*Hn + lane];
    const float gcnb = gcn_b[lane];
    const float lng = ln_g[lane], lnb = ln_b[lane];
    const float awv = attn_w[lane], attnb = attn_b[0];

    if (warp == 0) {
        float vW[5] = {Wc0, Wc1, Wc2, Wc3, gcnb};
        #pragma unroll
        for (int i2 = 0; i2 < 5; i2++) {
            #pragma unroll
            for (int j2 = i2; j2 < 5; j2++) {
                float g = warp_sum(vW[i2] * vW[j2]);
                if (lane == 0) { s_G[i2*5+j2] = g; s_G[j2*5+i2] = g; }
            }
            float sw = warp_sum(vW[i2]);
            if (lane == 0) s_SWb[i2] = sw;
        }
    }

    // recurrence edge (tid-based)
    int rn = 0, rm = 1;
    const bool ract = (tid < 91);
    if (ract) edge_map(tid, rn, rm);
    float ee = 0.0f;

    // per-warp online softmax state (lane = channel)
    float Pol = 0.0f, Mol = -1e30f, Sol = 0.0f;

    const float4* src = reinterpret_cast<const float4*>(ws) + (size_t)b * (Tn * Nn);

    for (int ch = 0; ch < Tn / CH; ch++) {
        const int t0 = ch * CH;
        __syncthreads();     // protects s_nrm/s_esmF reuse (+ s_G first iter)

        // ---- cooperative load + normalize: CH steps x 14 nodes ----
        #pragma unroll
        for (int r2 = 0; r2 < 2; r2++) {
            int off = r2 * 128 + tid;
            if (off < CH * Nn) {
                float4 v = src[t0 * Nn + off];
                float d2 = v.x*v.x + v.y*v.y + v.z*v.z + v.w*v.w;
                float inv = rsqrtf(fmaxf(d2, 1e-24f));
                int tl2 = off / 14;
                int nd  = off - tl2 * 14;
                s_nrm[tl2][nd] = make_float4(v.x*inv, v.y*inv, v.z*inv, v.w*inv);
                s_len[tl2][nd] = d2 * inv;   // = |de|
            }
        }
        __syncthreads();

        // ---- edge recurrence: CH steps, write symmetric matrix ----
        if (ract) {
            #pragma unroll 4
            for (int k = 0; k < CH; k++) {
                float4 a  = s_nrm[k][rn];
                float4 c4 = s_nrm[k][rm];
                float dot = a.x * c4.x;
                dot = fmaf(a.y, c4.y, dot);
                dot = fmaf(a.z, c4.z, dot);
                dot = fmaf(a.w, c4.w, dot);
                float adj = fmaf(dot, 0.5f, 0.5f);
                float xg = fmaf(gw0, ee, fmaf(gw1, adj, gbv));
                float z  = sigmoid_fast(xg);
                ee = fmaf(z, adj - ee, ee);
                s_esmF[k][rn * RS + rm] = ee;
                s_esmF[k][rm * RS + rn] = ee;
            }
        } else if (tid < 105) {
            const int d = tid - 91;
            #pragma unroll
            for (int k = 0; k < CH; k++) s_esmF[k][d * (RS + 1)] = 0.0f;
        }
        __syncthreads();

        // ---- tasks: 2 rounds, dual-task half-warps ----
        #pragma unroll 1
        for (int j = 0; j < 2; j++) {
            const int tl = 8 * j + 2 * warp + half;
            const float* rowp = &s_esmF[tl][c * RS];
            const bool act = (c < 14);

            // phase A: rowsum -> dis, q   (vectorized row read)
            float dis = 0.0f;
            float4 de4 = make_float4(0.f,0.f,0.f,0.f);
            if (act) {
                float4 e0 = *reinterpret_cast<const float4*>(rowp);
                float4 e1 = *reinterpret_cast<const float4*>(rowp + 4);
                float4 e2 = *reinterpret_cast<const float4*>(rowp + 8);
                float2 e3 = *reinterpret_cast<const float2*>(rowp + 12);
                float rs = 1.0f + e0.x + e0.y + e0.z + e0.w
                                + e1.x + e1.y + e1.z + e1.w
                                + e2.x + e2.y + e2.z + e2.w
                                + e3.x + e3.y;
                dis = rsqrtf(fmaxf(rs, 1e-6f));
                float4 nr = s_nrm[tl][c];
                float f = s_len[tl][c] * dis;
                de4 = make_float4(nr.x*f, nr.y*f, nr.z*f, nr.w*f);
                s_q[warp][half][c] = de4;
                s_dis[warp][half][c] = dis;
            }
            __syncwarp();

            // phase B: matvec + LN stats
            if (act) {
                float4 e0 = *reinterpret_cast<const float4*>(rowp);
                float4 e1 = *reinterpret_cast<const float4*>(rowp + 4);
                float4 e2 = *reinterpret_cast<const float4*>(rowp + 8);
                float2 e3 = *reinterpret_cast<const float2*>(rowp + 12);
                float er[14] = {e0.x,e0.y,e0.z,e0.w, e1.x,e1.y,e1.z,e1.w,
                                e2.x,e2.y,e2.z,e2.w, e3.x,e3.y};
                float4 p = make_float4(0.f,0.f,0.f,0.f);
                float racc = 0.0f;
                #pragma unroll
                for (int m3 = 0; m3 < 14; m3++) {
                    float em  = er[m3];
                    float4 qm = s_q[warp][half][m3];
                    float dm  = s_dis[warp][half][m3];
                    p.x = fmaf(em, qm.x, p.x);
                    p.y = fmaf(em, qm.y, p.y);
                    p.z = fmaf(em, qm.z, p.z);
                    p.w = fmaf(em, qm.w, p.w);
                    racc = fmaf(em, dm, racc);
                }
                float rr = dis * (racc + dis);
                float x0 = (p.x + de4.x) * dis;
                float x1 = (p.y + de4.y) * dis;
                float x2 = (p.z + de4.z) * dis;
                float x3 = (p.w + de4.w) * dis;
                float mu = (x0*s_SWb[0] + x1*s_SWb[1] + x2*s_SWb[2]
                          + x3*s_SWb[3] + rr*s_SWb[4]) * (1.0f/32.0f);
                float xt[5] = {x0, x1, x2, x3, rr};
                float s2 = 0.0f;
                #pragma unroll
                for (int ii = 0; ii < 5; ii++) {
                    float rowd = 0.0f;
                    #pragma unroll
                    for (int jj = 0; jj < 5; jj++)
                        rowd = fmaf(s_G[ii*5+jj], xt[jj], rowd);
                    s2 = fmaf(xt[ii], rowd, s2);
                }
                s2 *= (1.0f/32.0f);
                float var  = fmaf(-mu, mu, s2);
                float istd = rsqrtf(var + 1e-5f);
                s_xp[warp][half][c] = make_float4(x0*istd, x1*istd, x2*istd, x3*istd);
                s_mr[warp][half][c] = make_float2(rr*istd, mu*istd);
            }
            __syncwarp();

            // phase C: LN apply + ELU + node mean, BOTH tasks (full warp, ILP 2)
            float acc0 = 0.0f, acc1 = 0.0f;
            #pragma unroll
            for (int nq = 0; nq < 14; nq++) {
                float4 xa = s_xp[warp][0][nq];
                float2 ma = s_mr[warp][0][nq];
                float4 xb = s_xp[warp][1][nq];
                float2 mb = s_mr[warp][1][nq];
                float ha = -ma.y;
                ha = fmaf(xa.x, Wc0, ha);
                ha = fmaf(xa.y, Wc1, ha);
                ha = fmaf(xa.z, Wc2, ha);
                ha = fmaf(xa.w, Wc3, ha);
                ha = fmaf(ma.x, gcnb, ha);
                acc0 += elu(fmaf(ha, lng, lnb));
                float hb = -mb.y;
                hb = fmaf(xb.x, Wc0, hb);
                hb = fmaf(xb.y, Wc1, hb);
                hb = fmaf(xb.z, Wc2, hb);
                hb = fmaf(xb.w, Wc3, hb);
                acc1 += elu(fmaf(fmaf(mb.x, gcnb, hb), lng, lnb));
            }
            float ge0 = acc0 * (1.0f / 14.0f);
            float ge1 = acc1 * (1.0f / 14.0f);

            // online softmax updates (task A then task B; order-free result)
            float sc0 = warp_sum(ge0 * awv) + attnb;
            {
                float nM = fmaxf(Mol, sc0);
                float al = __expf(Mol - nM);
                float wt = __expf(sc0 - nM);
                Pol = fmaf(Pol, al, wt * ge0);
                Sol = fmaf(Sol, al, wt);
                Mol = nM;
            }
            float sc1 = warp_sum(ge1 * awv) + attnb;
            {
                float nM = fmaxf(Mol, sc1);
                float al = __expf(Mol - nM);
                float wt = __expf(sc1 - nM);
                Pol = fmaf(Pol, al, wt * ge1);
                Sol = fmaf(Sol, al, wt);
                Mol = nM;
            }
            __syncwarp();
        }
    }

    // ---- publish per-warp pool state ----
    s_pool[warp][lane] = Pol;
    if (lane == 0) s_MS[warp] = make_float2(Mol, Sol);
    __syncthreads();
    // final esm matrix: s_esmF[CH-1] (t=255), symmetric, zero diag. Ready.

    if (warp == 0) {
        // ---- combine 4 online-softmax partials (exact) ----
        float2 ms0 = s_MS[0], ms1 = s_MS[1], ms2 = s_MS[2], ms3 = s_MS[3];
        float M = fmaxf(fmaxf(ms0.x, ms1.x), fmaxf(ms2.x, ms3.x));
        float f0 = __expf(ms0.x - M), f1 = __expf(ms1.x - M);
        float f2 = __expf(ms2.x - M), f3 = __expf(ms3.x - M);
        float P = s_pool[0][lane]*f0 + s_pool[1][lane]*f1
                + s_pool[2][lane]*f2 + s_pool[3][lane]*f3;
        float S = ms0.y*f0 + ms1.y*f1 + ms2.y*f2 + ms3.y*f3;
        s_comb[5 + lane] = __fdividef(P, S);
    } else if (warp == 3) {
        // ---- warp-local parallel Jacobi on s_esmF[CH-1]: 6 sweeps ----
        float* sf = s_esmF[CH - 1];
        int rowi[4], kki[4];
        #pragma unroll
        for (int ii = 0; ii < 4; ii++) {
            int idx = lane + 32 * ii;
            rowi[ii] = idx / 7;
            kki[ii]  = idx - rowi[ii] * 7;
        }
        for (int sweep = 0; sweep < 6; sweep++) {
            for (int r = 0; r < 13; r++) {
                if (lane < 7) {
                    int pj = (lane == 0) ? 0 : 1 + (lane - 1 + r) % 13;
                    int qj = 1 + (12 - lane + r) % 13;
                    float apq = sf[pj*RS + qj];
                    float app = sf[pj*(RS+1)];
                    float aqq = sf[qj*(RS+1)];
                    float ap  = fabsf(apq);
                    float den = (ap > 1e-20f) ? apq : 1.0f;
                    float theta = __fdividef(0.5f * (aqq - app), den);
                    float tt = __fdividef(1.0f, fabsf(theta) + sqrtf(fmaf(theta, theta, 1.0f)));
                    tt = (theta < 0.0f) ? -tt : tt;
                    tt = (ap > 1e-20f) ? tt : 0.0f;
                    float cc = rsqrtf(fmaf(tt, tt, 1.0f));
                    s_cs[lane] = make_float2(cc, tt * cc);
                    s_pq[lane] = make_int2(pj, qj);
                }
                __syncwarp();
                #pragma unroll
                for (int ii = 0; ii < 4; ii++) {
                    int idx = lane + 32 * ii;
                    if (idx < 98) {
                        float2 cs = s_cs[kki[ii]];
                        int2   pq = s_pq[kki[ii]];
                        int row = rowi[ii];
                        float a1 = sf[row*RS + pq.x];
                        float a2 = sf[row*RS + pq.y];
                        sf[row*RS + pq.x] = cs.x * a1 - cs.y * a2;
                        sf[row*RS + pq.y] = fmaf(cs.y, a1, cs.x * a2);
                    }
                }
                __syncwarp();
                #pragma unroll
                for (int ii = 0; ii < 4; ii++) {
                    int idx = lane + 32 * ii;
                    if (idx < 98) {
                        float2 cs = s_cs[kki[ii]];
                        int2   pq = s_pq[kki[ii]];
                        int col = rowi[ii];
                        float a1 = sf[pq.x*RS + col];
                        float a2 = sf[pq.y*RS + col];
                        sf[pq.x*RS + col] = cs.x * a1 - cs.y * a2;
                        sf[pq.y*RS + col] = fmaf(cs.y, a1, cs.x * a2);
                    }
                }
                __syncwarp();
            }
        }
        // top-5 eigenvalues ascending via parallel rank
        float ev = (lane < 14) ? sf[lane * (RS+1)] : 1e30f;
        int rank = 0;
        #pragma unroll
        for (int j2 = 0; j2 < 14; j2++) {
            float evj = sf[j2 * (RS+1)];
            rank += (evj < ev || (evj == ev && j2 < lane)) ? 1 : 0;
        }
        if (lane < 14 && rank >= 9) s_comb[rank - 9] = ev;
    }
    __syncthreads();

    // ---- classifier: 37 -> 64 (elu) -> 32 (elu) -> 2 ----
    if (tid < 64) {
        float a = c1_b[tid];
        #pragma unroll
        for (int i = 0; i < 37; i++)
            a = fmaf(s_comb[i], c1_w[i * 64 + tid], a);
        s_b1[tid] = elu(a);
    }
    __syncthreads();
    if (tid < 32) {
        float a2 = c2_b[lane];
        #pragma unroll
        for (int i = 0; i < 64; i++)
            a2 = fmaf(s_b1[i], c2_w[i * 32 + lane], a2);
        float h2 = elu(a2);
        float r0 = warp_sum(h2 * c3_w[lane * 2 + 0]);
        float r1 = warp_sum(h2 * c3_w[lane * 2 + 1]);
        if (lane == 0) {
            out[b * 2 + 0] = r0 + c3_b[0];
            out[b * 2 + 1] = r1 + c3_b[1];
        }
    }
}

extern "C" void kernel_launch(void* const* d_in, const int* in_sizes, int n_in,
                              void* d_out, int out_size)
{
    const float* ws     = (const float*)d_in[0];
    const float* gate_w = (const float*)d_in[1];
    const float* gate_b = (const float*)d_in[2];
    const float* gcn_w  = (const float*)d_in[3];
    const float* gcn_b  = (const float*)d_in[4];
    const float* ln_g   = (const float*)d_in[5];
    const float* ln_b   = (const float*)d_in[6];
    const float* attn_w = (const float*)d_in[7];
    const float* attn_b = (const float*)d_in[8];
    const float* c1_w   = (const float*)d_in[9];
    const float* c1_b   = (const float*)d_in[10];
    const float* c2_w   = (const float*)d_in[11];
    const float* c2_b   = (const float*)d_in[12];
    const float* c3_w   = (const float*)d_in[13];
    const float* c3_b   = (const float*)d_in[14];
    float* out = (float*)d_out;

    tgsm_fused<<<Bn, 128>>>(ws, gate_w, gate_b, gcn_w, gcn_b, ln_g, ln_b,
                            attn_w, attn_b, c1_w, c1_b, c2_w, c2_b,
                            c3_w, c3_b, out);
}